// round 10
// baseline (speedup 1.0000x reference)
#include <cuda_runtime.h>
#include <cstdint>

#define SQ 512
#define NSEQ 512
#define CM 64
#define CZ 128
#define NH 8
#define EPS 1e-5f

// Scratch (device globals: allocation-free)
__device__ float g_w[(size_t)SQ * NH * SQ];        // raw logits [i][h][j]
__device__ float g_whf[(size_t)SQ * NH * SQ];      // w hi, A-frag layout [I][h][jg][lane][4]
__device__ float g_vTf[(size_t)CM * NSEQ * SQ];    // v, B-frag layout [h][ndg][jg][lane][2]
__device__ float g_gT[(size_t)CM * NSEQ * SQ];     // gate [(c*512+n)*512 + s]
__device__ float g_o2[(size_t)CM * NSEQ * SQ];     // gated o, [(c*512+n)*512 + i]

__device__ __forceinline__ float warp_sum(float v) {
#pragma unroll
    for (int o = 16; o > 0; o >>= 1) v += __shfl_xor_sync(0xffffffffu, v, o);
    return v;
}
__device__ __forceinline__ uint32_t smem_u32(const void* p) {
    uint32_t a;
    asm("{ .reg .u64 t; cvta.to.shared.u64 t, %1; cvt.u32.u64 %0, t; }" : "=r"(a) : "l"(p));
    return a;
}
__device__ __forceinline__ float tf32rn(float x) {
    uint32_t r;
    asm("cvt.rna.tf32.f32 %0, %1;" : "=r"(r) : "f"(x));
    return __uint_as_float(r);
}
__device__ __forceinline__ void mma_tf32(float* d, const uint32_t* a,
                                         uint32_t b0, uint32_t b1) {
    asm volatile(
        "mma.sync.aligned.m16n8k8.row.col.f32.tf32.tf32.f32 "
        "{%0,%1,%2,%3}, {%4,%5,%6,%7}, {%8,%9}, {%0,%1,%2,%3};"
        : "+f"(d[0]), "+f"(d[1]), "+f"(d[2]), "+f"(d[3])
        : "r"(a[0]), "r"(a[1]), "r"(a[2]), "r"(a[3]), "r"(b0), "r"(b1));
}
#define CP_ASYNC16(dst, src) \
    asm volatile("cp.async.cg.shared.global [%0], [%1], 16;" :: "r"(dst), "l"(src))
#define CP_COMMIT() asm volatile("cp.async.commit_group;")
#define CP_WAIT(n)  asm volatile("cp.async.wait_group %0;" :: "n"(n))

// swizzled float index (used by vg phase-2 only)
__device__ __forceinline__ int fidx32(int row, int k) {
    return row * 32 + ((((k >> 2) ^ (row & 7)) << 2) | (k & 3));
}

// ---------------------------------------------------------------------------
// Kernel 1: b[i,h,j] = LN(z[i,j,:]) . W_b[h,:] -> g_w.  (R8 version, proven)
// ---------------------------------------------------------------------------
__global__ __launch_bounds__(256) void bias_ln_kernel(
    const float* __restrict__ z, const float* __restrict__ lnw,
    const float* __restrict__ lnb, const float* __restrict__ Wb)
{
    __shared__ float zn[64 * 132];
    __shared__ float swb[8 * 132];
    __shared__ float bs[2 * 64 * 8];
    int tid = threadIdx.x, wid = tid >> 5, lane = tid & 31;
    int g = lane >> 2, tg = lane & 3;

    {
        int h = tid >> 5;
        *(float4*)(swb + h * 132 + lane * 4) = *(const float4*)(Wb + h * CZ + lane * 4);
    }
    float4 lw = *(const float4*)(lnw + lane * 4);
    float4 lb = *(const float4*)(lnb + lane * 4);

    size_t R0 = (size_t)blockIdx.x * 64;
#pragma unroll
    for (int rr = 0; rr < 8; ++rr) {
        int row = wid * 8 + rr;
        float4 x = *(const float4*)(z + (R0 + row) * CZ + lane * 4);
        float s = warp_sum(x.x + x.y + x.z + x.w);
        float mu = s * (1.0f / CZ);
        float d0 = x.x - mu, d1 = x.y - mu, d2 = x.z - mu, d3 = x.w - mu;
        float q = warp_sum(d0 * d0 + d1 * d1 + d2 * d2 + d3 * d3);
        float rs = rsqrtf(q * (1.0f / CZ) + EPS);
        float4 nv;
        nv.x = d0 * rs * lw.x + lb.x;
        nv.y = d1 * rs * lw.y + lb.y;
        nv.z = d2 * rs * lw.z + lb.z;
        nv.w = d3 * rs * lw.w + lb.w;
        *(float4*)(zn + row * 132 + lane * 4) = nv;
    }
    __syncthreads();

    {
        int wmt = wid & 3, kh = wid >> 2;
        float acc[4] = {0.f, 0.f, 0.f, 0.f};
#pragma unroll
        for (int ks = 0; ks < 8; ++ks) {
            int k = kh * 64 + ks * 8;
            float a0 = zn[(wmt * 16 + g) * 132 + k + tg];
            float a1 = zn[(wmt * 16 + g + 8) * 132 + k + tg];
            float a2 = zn[(wmt * 16 + g) * 132 + k + tg + 4];
            float a3 = zn[(wmt * 16 + g + 8) * 132 + k + tg + 4];
            uint32_t ah[4], al[4];
            float h0 = tf32rn(a0), h1 = tf32rn(a1), h2 = tf32rn(a2), h3 = tf32rn(a3);
            ah[0] = __float_as_uint(h0); ah[1] = __float_as_uint(h1);
            ah[2] = __float_as_uint(h2); ah[3] = __float_as_uint(h3);
            al[0] = __float_as_uint(tf32rn(a0 - h0));
            al[1] = __float_as_uint(tf32rn(a1 - h1));
            al[2] = __float_as_uint(tf32rn(a2 - h2));
            al[3] = __float_as_uint(tf32rn(a3 - h3));
            float b0 = swb[g * 132 + k + tg];
            float b1 = swb[g * 132 + k + tg + 4];
            float bh0 = tf32rn(b0), bh1 = tf32rn(b1);
            uint32_t ubh0 = __float_as_uint(bh0), ubh1 = __float_as_uint(bh1);
            uint32_t ubl0 = __float_as_uint(tf32rn(b0 - bh0));
            uint32_t ubl1 = __float_as_uint(tf32rn(b1 - bh1));
            mma_tf32(acc, ah, ubh0, ubh1);
            mma_tf32(acc, al, ubh0, ubh1);
            mma_tf32(acc, ah, ubl0, ubl1);
        }
        int base = kh * 512 + (wmt * 16 + g) * 8 + 2 * tg;
        bs[base] = acc[0];
        bs[base + 1] = acc[1];
        bs[base + 64] = acc[2];
        bs[base + 65] = acc[3];
    }
    __syncthreads();
    {
        int h = tid >> 6, row = tid & 63;
        float v = bs[row * 8 + h] + bs[512 + row * 8 + h];
        float v2 = bs[row * 8 + h + 4] + bs[512 + row * 8 + h + 4];
        int i = (int)(R0 >> 9), j0 = (int)(R0 & 511);
        g_w[(size_t)i * 4096 + h * 512 + j0 + row] = v;
        g_w[(size_t)i * 4096 + (h + 4) * 512 + j0 + row] = v2;
    }
}

// ---------------------------------------------------------------------------
// Kernel 2: softmax over j; emits A-fragment-layout hi slab only.
// ---------------------------------------------------------------------------
#define SMX_SMEMB (8704 * 4)
__global__ __launch_bounds__(256, 1) void softmax_kernel()
{
    extern __shared__ float sx[];
    float* smh = sx;
    int tid = threadIdx.x;
    int row = tid >> 4, l = tid & 15;
    int I = blockIdx.x >> 3, h = blockIdx.x & 7;
    const float* src = g_w + ((size_t)(I * 16 + row)) * 4096 + h * 512;

    float w[32];
    float mx = -1e30f;
#pragma unroll
    for (int jj = 0; jj < 32; ++jj) {
        w[jj] = src[jj * 16 + l];
        mx = fmaxf(mx, w[jj]);
    }
#pragma unroll
    for (int o = 8; o > 0; o >>= 1) mx = fmaxf(mx, __shfl_xor_sync(0xffffffffu, mx, o));
    float sum = 0.f;
#pragma unroll
    for (int jj = 0; jj < 32; ++jj) {
        w[jj] = __expf(w[jj] - mx);
        sum += w[jj];
    }
#pragma unroll
    for (int o = 8; o > 0; o >>= 1) sum += __shfl_xor_sync(0xffffffffu, sum, o);
    float inv = 1.0f / sum;
#pragma unroll
    for (int jj = 0; jj < 32; ++jj) {
        int j = jj * 16 + l;
        smh[j * 17 + row] = tf32rn(w[jj] * inv);
    }
    __syncthreads();

    float* dh = g_whf + (size_t)(I * 8 + h) * 8192;
#pragma unroll
    for (int it = 0; it < 8; ++it) {
        int u = it * 256 + tid;
        int jg = u >> 5, lane = u & 31;
        float4 vh;
#pragma unroll
        for (int idx = 0; idx < 4; ++idx) {
            int il = (lane >> 2) + (idx & 1) * 8;
            int j = jg * 8 + ((idx >> 1) & 1) * 4 + (lane & 3);
            (&vh.x)[idx] = smh[j * 17 + il];
        }
        *(float4*)(dh + u * 4) = vh;
    }
}

// ---------------------------------------------------------------------------
// Kernel 3: fused LN(m) -> 1-term mma -> vT (B-frag layout) + gate.
// ---------------------------------------------------------------------------
#define VG_AH 0
#define VG_BH 8192
#define VG_SMEMB (16896 * 4)

__global__ __launch_bounds__(256, 1) void vg_kernel(
    const float* __restrict__ m, const float* __restrict__ lnw,
    const float* __restrict__ lnb, const float* __restrict__ Wv,
    const float* __restrict__ Wg)
{
    extern __shared__ float sm[];
    int tid = threadIdx.x, wid = tid >> 5, lane = tid & 31;
    int g = lane >> 2, tg = lane & 3;
    int n = blockIdx.x, s0 = blockIdx.y * 128;

    {   // phase 1: LN + tf32 round to swizzled smem (hi only)
        int row = tid >> 1, half = tid & 1;
        const float* src = m + ((size_t)(s0 + row) * 512 + n) * CM + half * 32;
        float v[32];
        float s = 0.f, q = 0.f;
#pragma unroll
        for (int qd = 0; qd < 8; ++qd) {
            float4 a = *(const float4*)(src + qd * 4);
            v[qd * 4 + 0] = a.x; v[qd * 4 + 1] = a.y;
            v[qd * 4 + 2] = a.z; v[qd * 4 + 3] = a.w;
            s += a.x + a.y + a.z + a.w;
            q += a.x * a.x + a.y * a.y + a.z * a.z + a.w * a.w;
        }
        s += __shfl_xor_sync(0xffffffffu, s, 1);
        q += __shfl_xor_sync(0xffffffffu, q, 1);
        float mu = s * (1.0f / CM);
        float var = q * (1.0f / CM) - mu * mu;
        float rs = rsqrtf(var + EPS);
#pragma unroll
        for (int qd = 0; qd < 8; ++qd) {
            int kq = half * 8 + qd;
            float xs[4];
#pragma unroll
            for (int t = 0; t < 4; ++t) {
                int k = kq * 4 + t;
                xs[t] = (v[qd * 4 + t] - mu) * rs * __ldg(lnw + k) + __ldg(lnb + k);
            }
            float4 hi = make_float4(tf32rn(xs[0]), tf32rn(xs[1]), tf32rn(xs[2]), tf32rn(xs[3]));
            int f4 = (kq >> 3) * 1024 + row * 8 + ((kq & 7) ^ (row & 7));
            *(float4*)(sm + VG_AH + f4 * 4) = hi;
        }
        const float* wsrc = (row < 64) ? (Wv + row * 64) : (Wg + (row - 64) * 64);
#pragma unroll
        for (int qd = 0; qd < 8; ++qd) {
            int kq = half * 8 + qd;
            float4 a = *(const float4*)(wsrc + kq * 4);
            float4 hi = make_float4(tf32rn(a.x), tf32rn(a.y), tf32rn(a.z), tf32rn(a.w));
            int f4 = (kq >> 3) * 1024 + row * 8 + ((kq & 7) ^ (row & 7));
            *(float4*)(sm + VG_BH + f4 * 4) = hi;
        }
    }
    __syncthreads();

    // phase 2: 1-term mma
    int wi = (wid & 3) * 32, wn = (wid >> 2) * 64;
    float acc[2][8][4];
#pragma unroll
    for (int mt = 0; mt < 2; ++mt)
#pragma unroll
        for (int nt = 0; nt < 8; ++nt)
#pragma unroll
            for (int r = 0; r < 4; ++r) acc[mt][nt][r] = 0.f;

#pragma unroll
    for (int k8 = 0; k8 < 8; ++k8) {
        int kb = k8 * 8;
        int sec = (kb >> 5) * 4096;
        int kl = kb & 31;
        uint32_t ah[2][4];
#pragma unroll
        for (int mt = 0; mt < 2; ++mt) {
            int r0 = wi + mt * 16 + g;
            ah[mt][0] = __float_as_uint(sm[VG_AH + sec + fidx32(r0, kl + tg)]);
            ah[mt][1] = __float_as_uint(sm[VG_AH + sec + fidx32(r0 + 8, kl + tg)]);
            ah[mt][2] = __float_as_uint(sm[VG_AH + sec + fidx32(r0, kl + 4 + tg)]);
            ah[mt][3] = __float_as_uint(sm[VG_AH + sec + fidx32(r0 + 8, kl + 4 + tg)]);
        }
#pragma unroll
        for (int nt = 0; nt < 8; ++nt) {
            int n0 = wn + nt * 8 + g;
            uint32_t b0 = __float_as_uint(sm[VG_BH + sec + fidx32(n0, kl + tg)]);
            uint32_t b1 = __float_as_uint(sm[VG_BH + sec + fidx32(n0, kl + 4 + tg)]);
#pragma unroll
            for (int mt = 0; mt < 2; ++mt)
                mma_tf32(acc[mt][nt], ah[mt], b0, b1);
        }
    }
    __syncthreads();

    // phase 3: epilogue
    float* Cs = sm;
    float* Cg2 = sm + 8448;
#pragma unroll
    for (int mt = 0; mt < 2; ++mt) {
        int r = wi + mt * 16 + g;
#pragma unroll
        for (int nt = 0; nt < 8; ++nt) {
            int col = wn + nt * 8 + 2 * tg;
            if (wid < 4) {
                Cs[col * 132 + r]            = acc[mt][nt][0];
                Cs[(col + 1) * 132 + r]      = acc[mt][nt][1];
                Cs[col * 132 + r + 8]        = acc[mt][nt][2];
                Cs[(col + 1) * 132 + r + 8]  = acc[mt][nt][3];
            } else {
                int cl = col - 64;
                Cg2[cl * 132 + r]            = 1.0f / (1.0f + __expf(-acc[mt][nt][0]));
                Cg2[(cl + 1) * 132 + r]      = 1.0f / (1.0f + __expf(-acc[mt][nt][1]));
                Cg2[cl * 132 + r + 8]        = 1.0f / (1.0f + __expf(-acc[mt][nt][2]));
                Cg2[(cl + 1) * 132 + r + 8]  = 1.0f / (1.0f + __expf(-acc[mt][nt][3]));
            }
        }
    }
    __syncthreads();
#pragma unroll
    for (int it = 0; it < 16; ++it) {
        int u = it * 256 + tid;
        int c = u >> 6, rem = u & 63;
        int jgl = rem >> 2, j3 = rem & 3;
        int sl = jgl * 8 + j3;
        float v0 = tf32rn(Cs[c * 132 + sl]);
        float v1 = tf32rn(Cs[c * 132 + sl + 4]);
        int d = c & 7, hh = c >> 3;
        int ndg = d * 64 + (n >> 3);
        int gpos = n & 7;
        size_t off = (((size_t)hh * 512 + ndg) * 64 + (size_t)((s0 >> 3) + jgl)) * 64
                   + (gpos * 4 + j3) * 2;
        *(float2*)(g_vTf + off) = make_float2(v0, v1);
    }
#pragma unroll
    for (int it = 0; it < 8; ++it) {
        int idx = it * 256 + tid;
        int c = idx >> 5, sq = idx & 31;
        *(float4*)(g_gT + ((size_t)c * 512 + n) * 512 + s0 + sq * 4) =
            *(const float4*)(Cg2 + c * 132 + sq * 4);
    }
}

// ---------------------------------------------------------------------------
// Kernel 4: pwa 1-term TF32 mma, 4-stage ring, ONE sync per chunk.
// Block 512 thr: M=256(i) x N=128(nd), K=512, kc=32. Stage 48KB x4 = 192KB.
// ---------------------------------------------------------------------------
#define PW_STGF 12288
#define PW_STGB 49152
#define PW_SMEMB (4 * PW_STGB)

__device__ __forceinline__ void pw_ldstage(uint32_t sb, int tid,
                                           const float* Ah_g, const float* Bg,
                                           int chunk)
{
    int jg0 = chunk * 4;
#pragma unroll
    for (int it = 0; it < 4; ++it) {
        int t = it * 512 + tid;
        int Igl = t >> 7, rem = t & 127;
        int jgl = rem >> 5, part = rem & 31;
        size_t src = (size_t)Igl * 65536 + (jg0 + jgl) * 128 + part * 4;
        CP_ASYNC16(sb + (uint32_t)t * 16, Ah_g + src);
    }
#pragma unroll
    for (int it = 0; it < 2; ++it) {
        int t = it * 512 + tid;
        int ndgl = t >> 6, rem = t & 63;
        int jgl = rem >> 4, part = rem & 15;
        size_t src = (size_t)ndgl * 4096 + (jg0 + jgl) * 64 + part * 4;
        CP_ASYNC16(sb + 32768 + (uint32_t)t * 16, Bg + src);
    }
}

__global__ __launch_bounds__(512, 1) void pwa_mma_kernel()
{
    extern __shared__ float sm[];
    uint32_t sbase = smem_u32(sm);
    int tid = threadIdx.x, wid = tid >> 5, lane = tid & 31;
    int g = lane >> 2, tg = lane & 3;
    int h = blockIdx.z;
    int i0 = blockIdx.y * 256;
    int nd0 = blockIdx.x * 128;
    const float* Ah_g = g_whf + (size_t)((i0 >> 4) * 8 + h) * 8192;
    const float* Bg   = g_vTf + (size_t)(h * 512 + (nd0 >> 3)) * 4096;

    int iw = (wid & 3) * 4;
    int nw = (wid >> 2) * 4;
    int wi = (wid & 3) * 64, wn = (wid >> 2) * 32;

    float acc[4][4][4];
#pragma unroll
    for (int mt = 0; mt < 4; ++mt)
#pragma unroll
        for (int nt = 0; nt < 4; ++nt)
#pragma unroll
            for (int r = 0; r < 4; ++r) acc[mt][nt][r] = 0.f;

    pw_ldstage(sbase, tid, Ah_g, Bg, 0);
    CP_COMMIT();
    pw_ldstage(sbase + PW_STGB, tid, Ah_g, Bg, 1);
    CP_COMMIT();
    pw_ldstage(sbase + 2 * PW_STGB, tid, Ah_g, Bg, 2);
    CP_COMMIT();

    for (int c = 0; c < 16; ++c) {
        if (c <= 13)      CP_WAIT(2);
        else if (c == 14) CP_WAIT(1);
        else              CP_WAIT(0);
        __syncthreads();
        if (c + 3 < 16) {
            pw_ldstage(sbase + ((c + 3) & 3) * PW_STGB, tid, Ah_g, Bg, c + 3);
            CP_COMMIT();
        }

        const float* Ah = sm + (c & 3) * PW_STGF;
        const float* Bh = Ah + 8192;
#pragma unroll
        for (int kk = 0; kk < 4; ++kk) {
            float4 ahv[4];
#pragma unroll
            for (int mt = 0; mt < 4; ++mt) {
                int blk = ((iw + mt) * 4 + kk) * 128 + lane * 4;
                ahv[mt] = *(const float4*)(Ah + blk);
            }
#pragma unroll
            for (int nt = 0; nt < 4; ++nt) {
                float2 bv = *(const float2*)(Bh + ((nw + nt) * 4 + kk) * 64 + lane * 2);
                uint32_t b0 = __float_as_uint(bv.x);
                uint32_t b1 = __float_as_uint(bv.y);
#pragma unroll
                for (int mt = 0; mt < 4; ++mt)
                    mma_tf32(acc[mt][nt], (const uint32_t*)&ahv[mt], b0, b1);
            }
        }
    }
    __syncthreads();

    // epilogue: stage C [col 128][260 rows], gate-multiply, coalesced store
    float* Cs = sm;
#pragma unroll
    for (int mt = 0; mt < 4; ++mt) {
        int r = wi + mt * 16 + g;
#pragma unroll
        for (int nt = 0; nt < 4; ++nt) {
            int col = wn + nt * 8 + 2 * tg;
            Cs[col * 260 + r]            = acc[mt][nt][0];
            Cs[(col + 1) * 260 + r]      = acc[mt][nt][1];
            Cs[col * 260 + r + 8]        = acc[mt][nt][2];
            Cs[(col + 1) * 260 + r + 8]  = acc[mt][nt][3];
        }
    }
    __syncthreads();
    size_t obase = ((size_t)h * 4096 + nd0) * 512 + i0;
#pragma unroll
    for (int it = 0; it < 16; ++it) {
        int idx = it * 512 + tid;
        int col = idx >> 6, rq = idx & 63;
        float4 ov = *(const float4*)(Cs + col * 260 + rq * 4);
        float4 gv = *(const float4*)(g_gT + obase + (size_t)col * 512 + rq * 4);
        ov.x *= gv.x; ov.y *= gv.y; ov.z *= gv.z; ov.w *= gv.w;
        *(float4*)(g_o2 + obase + (size_t)col * 512 + rq * 4) = ov;
    }
}

// ---------------------------------------------------------------------------
// Kernel 5: outT = Wout @ G via 1-term tf32 mma.
// A = Wout [co=64][k=64] row-major rounded; B = G [k=c][s=128] col-major (As2).
// ---------------------------------------------------------------------------
#define OUT_SMEMB ((8704 + 4352) * 4)

__global__ __launch_bounds__(256, 1) void out_kernel(
    const float* __restrict__ Wout, float* __restrict__ out)
{
    extern __shared__ float so[];
    float* As2 = so;            // [k=64][136]  (G, tf32-rounded)
    float* Wt  = so + 8704;     // [co=64][68]  (Wout, tf32-rounded)
    int tid = threadIdx.x, wid = tid >> 5, lane = tid & 31;
    int g = lane >> 2, tg = lane & 3;
    int n = blockIdx.x & 511, s0 = (blockIdx.x >> 9) * 128;

#pragma unroll
    for (int it = 0; it < 4; ++it) {     // Wout -> Wt rounded
        int idx = it * 256 + tid;
        int co = idx >> 4, cq = idx & 15;
        float4 a = *(const float4*)(Wout + co * 64 + cq * 4);
        Wt[co * 68 + cq * 4 + 0] = tf32rn(a.x);
        Wt[co * 68 + cq * 4 + 1] = tf32rn(a.y);
        Wt[co * 68 + cq * 4 + 2] = tf32rn(a.z);
        Wt[co * 68 + cq * 4 + 3] = tf32rn(a.w);
    }
#pragma unroll
    for (int it = 0; it < 8; ++it) {     // gated o2 -> As2 rounded
        int idx = it * 256 + tid;
        int c = idx >> 5, sq = idx & 31;
        float4 v = *(const float4*)(g_o2 + ((size_t)c * 512 + n) * 512 + s0 + sq * 4);
        As2[c * 136 + sq * 4 + 0] = tf32rn(v.x);
        As2[c * 136 + sq * 4 + 1] = tf32rn(v.y);
        As2[c * 136 + sq * 4 + 2] = tf32rn(v.z);
        As2[c * 136 + sq * 4 + 3] = tf32rn(v.w);
    }
    __syncthreads();

    int m0 = (wid & 3) * 16;      // c_out tile
    int n0 = (wid >> 2) * 64;     // s half
    float acc[8][4];
#pragma unroll
    for (int nt = 0; nt < 8; ++nt)
#pragma unroll
        for (int r = 0; r < 4; ++r) acc[nt][r] = 0.f;

#pragma unroll
    for (int k8 = 0; k8 < 8; ++k8) {
        int kb = k8 * 8;
        uint32_t a[4];
        a[0] = __float_as_uint(Wt[(m0 + g) * 68 + kb + tg]);
        a[1] = __float_as_uint(Wt[(m0 + g + 8) * 68 + kb + tg]);
        a[2] = __float_as_uint(Wt[(m0 + g) * 68 + kb + tg + 4]);
        a[3] = __float_as_uint(Wt[(m0 + g + 8) * 68 + kb + tg + 4]);
#pragma unroll
        for (int nt = 0; nt < 8; ++nt) {
            int col = n0 + nt * 8 + g;
            uint32_t b0 = __float_as_uint(As2[(kb + tg) * 136 + col]);
            uint32_t b1 = __float_as_uint(As2[(kb + tg + 4) * 136 + col]);
            mma_tf32(acc[nt], a, b0, b1);
        }
    }
    __syncthreads();

    float* Ds = so;               // [s=128][68], aliases As2
#pragma unroll
    for (int nt = 0; nt < 8; ++nt) {
        int colb = n0 + nt * 8 + 2 * tg;
        Ds[colb * 68 + m0 + g]           = acc[nt][0];
        Ds[(colb + 1) * 68 + m0 + g]     = acc[nt][1];
        Ds[colb * 68 + m0 + g + 8]       = acc[nt][2];
        Ds[(colb + 1) * 68 + m0 + g + 8] = acc[nt][3];
    }
    __syncthreads();
#pragma unroll
    for (int it = 0; it < 8; ++it) {
        int idx = it * 256 + tid;
        int s = idx >> 4, cq = idx & 15;
        *(float4*)(out + ((size_t)(s0 + s) * 512 + n) * CM + cq * 4) =
            *(const float4*)(Ds + s * 68 + cq * 4);
    }
}

// ---------------------------------------------------------------------------
extern "C" void kernel_launch(void* const* d_in, const int* in_sizes, int n_in,
                              void* d_out, int out_size)
{
    const float* m    = (const float*)d_in[0];
    const float* z    = (const float*)d_in[1];
    const float* lnmw = (const float*)d_in[2];
    const float* lnmb = (const float*)d_in[3];
    const float* lnzw = (const float*)d_in[4];
    const float* lnzb = (const float*)d_in[5];
    const float* Wv   = (const float*)d_in[6];
    const float* Wb   = (const float*)d_in[7];
    const float* Wg   = (const float*)d_in[8];
    const float* Wout = (const float*)d_in[9];
    float* out = (float*)d_out;

    cudaFuncSetAttribute(pwa_mma_kernel,
                         cudaFuncAttributeMaxDynamicSharedMemorySize, PW_SMEMB);
    cudaFuncSetAttribute(vg_kernel,
                         cudaFuncAttributeMaxDynamicSharedMemorySize, VG_SMEMB);
    cudaFuncSetAttribute(softmax_kernel,
                         cudaFuncAttributeMaxDynamicSharedMemorySize, SMX_SMEMB);
    cudaFuncSetAttribute(out_kernel,
                         cudaFuncAttributeMaxDynamicSharedMemorySize, OUT_SMEMB);

    bias_ln_kernel<<<SQ * SQ / 64, 256>>>(z, lnzw, lnzb, Wb);
    softmax_kernel<<<(SQ / 16) * NH, 256, SMX_SMEMB>>>();
    vg_kernel<<<dim3(512, 4), 256, VG_SMEMB>>>(m, lnmw, lnmb, Wv, Wg);
    dim3 gD(32, 2, NH);
    pwa_mma_kernel<<<gD, 512, PW_SMEMB>>>();
    out_kernel<<<SQ * NSEQ / 128, 256, OUT_SMEMB>>>(Wout, out);
}

// round 11
// speedup vs baseline: 1.4029x; 1.4029x over previous
#include <cuda_runtime.h>
#include <cstdint>

#define SQ 512
#define NSEQ 512
#define CM 64
#define CZ 128
#define NH 8
#define EPS 1e-5f

// Scratch (device globals: allocation-free)
__device__ float g_w[(size_t)SQ * NH * SQ];        // raw logits [i][h][j]
__device__ float g_whf[(size_t)SQ * NH * SQ];      // w hi, A-frag layout [I][h][jg][lane][4]
__device__ float g_vTf[(size_t)CM * NSEQ * SQ];    // v, B-frag layout [h][ndg][jg][lane][2]
__device__ float g_gT[(size_t)CM * NSEQ * SQ];     // gate [(c*512+n)*512 + s]
__device__ float g_o2[(size_t)CM * NSEQ * SQ];     // gated o, [(c*512+n)*512 + i]

__device__ __forceinline__ float warp_sum(float v) {
#pragma unroll
    for (int o = 16; o > 0; o >>= 1) v += __shfl_xor_sync(0xffffffffu, v, o);
    return v;
}
__device__ __forceinline__ uint32_t smem_u32(const void* p) {
    uint32_t a;
    asm("{ .reg .u64 t; cvta.to.shared.u64 t, %1; cvt.u32.u64 %0, t; }" : "=r"(a) : "l"(p));
    return a;
}
__device__ __forceinline__ float tf32rn(float x) {
    uint32_t r;
    asm("cvt.rna.tf32.f32 %0, %1;" : "=r"(r) : "f"(x));
    return __uint_as_float(r);
}
__device__ __forceinline__ void mma_tf32(float* d, const uint32_t* a,
                                         uint32_t b0, uint32_t b1) {
    asm volatile(
        "mma.sync.aligned.m16n8k8.row.col.f32.tf32.tf32.f32 "
        "{%0,%1,%2,%3}, {%4,%5,%6,%7}, {%8,%9}, {%0,%1,%2,%3};"
        : "+f"(d[0]), "+f"(d[1]), "+f"(d[2]), "+f"(d[3])
        : "r"(a[0]), "r"(a[1]), "r"(a[2]), "r"(a[3]), "r"(b0), "r"(b1));
}
#define CP_ASYNC16(dst, src) \
    asm volatile("cp.async.cg.shared.global [%0], [%1], 16;" :: "r"(dst), "l"(src))
#define CP_COMMIT() asm volatile("cp.async.commit_group;")
#define CP_WAIT(n)  asm volatile("cp.async.wait_group %0;" :: "n"(n))

// swizzled float index (used by vg phase-2 only)
__device__ __forceinline__ int fidx32(int row, int k) {
    return row * 32 + ((((k >> 2) ^ (row & 7)) << 2) | (k & 3));
}

// ---------------------------------------------------------------------------
// Kernel 1: b[i,h,j] = LN(z[i,j,:]) . W_b[h,:] -> g_w.  (R8 version, proven)
// ---------------------------------------------------------------------------
__global__ __launch_bounds__(256) void bias_ln_kernel(
    const float* __restrict__ z, const float* __restrict__ lnw,
    const float* __restrict__ lnb, const float* __restrict__ Wb)
{
    __shared__ float zn[64 * 132];
    __shared__ float swb[8 * 132];
    __shared__ float bs[2 * 64 * 8];
    int tid = threadIdx.x, wid = tid >> 5, lane = tid & 31;
    int g = lane >> 2, tg = lane & 3;

    {
        int h = tid >> 5;
        *(float4*)(swb + h * 132 + lane * 4) = *(const float4*)(Wb + h * CZ + lane * 4);
    }
    float4 lw = *(const float4*)(lnw + lane * 4);
    float4 lb = *(const float4*)(lnb + lane * 4);

    size_t R0 = (size_t)blockIdx.x * 64;
#pragma unroll
    for (int rr = 0; rr < 8; ++rr) {
        int row = wid * 8 + rr;
        float4 x = *(const float4*)(z + (R0 + row) * CZ + lane * 4);
        float s = warp_sum(x.x + x.y + x.z + x.w);
        float mu = s * (1.0f / CZ);
        float d0 = x.x - mu, d1 = x.y - mu, d2 = x.z - mu, d3 = x.w - mu;
        float q = warp_sum(d0 * d0 + d1 * d1 + d2 * d2 + d3 * d3);
        float rs = rsqrtf(q * (1.0f / CZ) + EPS);
        float4 nv;
        nv.x = d0 * rs * lw.x + lb.x;
        nv.y = d1 * rs * lw.y + lb.y;
        nv.z = d2 * rs * lw.z + lb.z;
        nv.w = d3 * rs * lw.w + lb.w;
        *(float4*)(zn + row * 132 + lane * 4) = nv;
    }
    __syncthreads();

    {
        int wmt = wid & 3, kh = wid >> 2;
        float acc[4] = {0.f, 0.f, 0.f, 0.f};
#pragma unroll
        for (int ks = 0; ks < 8; ++ks) {
            int k = kh * 64 + ks * 8;
            float a0 = zn[(wmt * 16 + g) * 132 + k + tg];
            float a1 = zn[(wmt * 16 + g + 8) * 132 + k + tg];
            float a2 = zn[(wmt * 16 + g) * 132 + k + tg + 4];
            float a3 = zn[(wmt * 16 + g + 8) * 132 + k + tg + 4];
            uint32_t ah[4], al[4];
            float h0 = tf32rn(a0), h1 = tf32rn(a1), h2 = tf32rn(a2), h3 = tf32rn(a3);
            ah[0] = __float_as_uint(h0); ah[1] = __float_as_uint(h1);
            ah[2] = __float_as_uint(h2); ah[3] = __float_as_uint(h3);
            al[0] = __float_as_uint(tf32rn(a0 - h0));
            al[1] = __float_as_uint(tf32rn(a1 - h1));
            al[2] = __float_as_uint(tf32rn(a2 - h2));
            al[3] = __float_as_uint(tf32rn(a3 - h3));
            float b0 = swb[g * 132 + k + tg];
            float b1 = swb[g * 132 + k + tg + 4];
            float bh0 = tf32rn(b0), bh1 = tf32rn(b1);
            uint32_t ubh0 = __float_as_uint(bh0), ubh1 = __float_as_uint(bh1);
            uint32_t ubl0 = __float_as_uint(tf32rn(b0 - bh0));
            uint32_t ubl1 = __float_as_uint(tf32rn(b1 - bh1));
            mma_tf32(acc, ah, ubh0, ubh1);
            mma_tf32(acc, al, ubh0, ubh1);
            mma_tf32(acc, ah, ubl0, ubl1);
        }
        int base = kh * 512 + (wmt * 16 + g) * 8 + 2 * tg;
        bs[base] = acc[0];
        bs[base + 1] = acc[1];
        bs[base + 64] = acc[2];
        bs[base + 65] = acc[3];
    }
    __syncthreads();
    {
        int h = tid >> 6, row = tid & 63;
        float v = bs[row * 8 + h] + bs[512 + row * 8 + h];
        float v2 = bs[row * 8 + h + 4] + bs[512 + row * 8 + h + 4];
        int i = (int)(R0 >> 9), j0 = (int)(R0 & 511);
        g_w[(size_t)i * 4096 + h * 512 + j0 + row] = v;
        g_w[(size_t)i * 4096 + (h + 4) * 512 + j0 + row] = v2;
    }
}

// ---------------------------------------------------------------------------
// Kernel 2: softmax over j; emits A-fragment-layout hi slab only.
// ---------------------------------------------------------------------------
#define SMX_SMEMB (8704 * 4)
__global__ __launch_bounds__(256, 1) void softmax_kernel()
{
    extern __shared__ float sx[];
    float* smh = sx;
    int tid = threadIdx.x;
    int row = tid >> 4, l = tid & 15;
    int I = blockIdx.x >> 3, h = blockIdx.x & 7;
    const float* src = g_w + ((size_t)(I * 16 + row)) * 4096 + h * 512;

    float w[32];
    float mx = -1e30f;
#pragma unroll
    for (int jj = 0; jj < 32; ++jj) {
        w[jj] = src[jj * 16 + l];
        mx = fmaxf(mx, w[jj]);
    }
#pragma unroll
    for (int o = 8; o > 0; o >>= 1) mx = fmaxf(mx, __shfl_xor_sync(0xffffffffu, mx, o));
    float sum = 0.f;
#pragma unroll
    for (int jj = 0; jj < 32; ++jj) {
        w[jj] = __expf(w[jj] - mx);
        sum += w[jj];
    }
#pragma unroll
    for (int o = 8; o > 0; o >>= 1) sum += __shfl_xor_sync(0xffffffffu, sum, o);
    float inv = 1.0f / sum;
#pragma unroll
    for (int jj = 0; jj < 32; ++jj) {
        int j = jj * 16 + l;
        smh[j * 17 + row] = tf32rn(w[jj] * inv);
    }
    __syncthreads();

    float* dh = g_whf + (size_t)(I * 8 + h) * 8192;
#pragma unroll
    for (int it = 0; it < 8; ++it) {
        int u = it * 256 + tid;
        int jg = u >> 5, lane = u & 31;
        float4 vh;
#pragma unroll
        for (int idx = 0; idx < 4; ++idx) {
            int il = (lane >> 2) + (idx & 1) * 8;
            int j = jg * 8 + ((idx >> 1) & 1) * 4 + (lane & 3);
            (&vh.x)[idx] = smh[j * 17 + il];
        }
        *(float4*)(dh + u * 4) = vh;
    }
}

// ---------------------------------------------------------------------------
// Kernel 3: fused LN(m) -> 1-term mma -> vT (B-frag layout) + gate.
// ---------------------------------------------------------------------------
#define VG_AH 0
#define VG_BH 8192
#define VG_SMEMB (16896 * 4)

__global__ __launch_bounds__(256, 1) void vg_kernel(
    const float* __restrict__ m, const float* __restrict__ lnw,
    const float* __restrict__ lnb, const float* __restrict__ Wv,
    const float* __restrict__ Wg)
{
    extern __shared__ float sm[];
    int tid = threadIdx.x, wid = tid >> 5, lane = tid & 31;
    int g = lane >> 2, tg = lane & 3;
    int n = blockIdx.x, s0 = blockIdx.y * 128;

    {   // phase 1: LN + tf32 round to swizzled smem (hi only)
        int row = tid >> 1, half = tid & 1;
        const float* src = m + ((size_t)(s0 + row) * 512 + n) * CM + half * 32;
        float v[32];
        float s = 0.f, q = 0.f;
#pragma unroll
        for (int qd = 0; qd < 8; ++qd) {
            float4 a = *(const float4*)(src + qd * 4);
            v[qd * 4 + 0] = a.x; v[qd * 4 + 1] = a.y;
            v[qd * 4 + 2] = a.z; v[qd * 4 + 3] = a.w;
            s += a.x + a.y + a.z + a.w;
            q += a.x * a.x + a.y * a.y + a.z * a.z + a.w * a.w;
        }
        s += __shfl_xor_sync(0xffffffffu, s, 1);
        q += __shfl_xor_sync(0xffffffffu, q, 1);
        float mu = s * (1.0f / CM);
        float var = q * (1.0f / CM) - mu * mu;
        float rs = rsqrtf(var + EPS);
#pragma unroll
        for (int qd = 0; qd < 8; ++qd) {
            int kq = half * 8 + qd;
            float xs[4];
#pragma unroll
            for (int t = 0; t < 4; ++t) {
                int k = kq * 4 + t;
                xs[t] = (v[qd * 4 + t] - mu) * rs * __ldg(lnw + k) + __ldg(lnb + k);
            }
            float4 hi = make_float4(tf32rn(xs[0]), tf32rn(xs[1]), tf32rn(xs[2]), tf32rn(xs[3]));
            int f4 = (kq >> 3) * 1024 + row * 8 + ((kq & 7) ^ (row & 7));
            *(float4*)(sm + VG_AH + f4 * 4) = hi;
        }
        const float* wsrc = (row < 64) ? (Wv + row * 64) : (Wg + (row - 64) * 64);
#pragma unroll
        for (int qd = 0; qd < 8; ++qd) {
            int kq = half * 8 + qd;
            float4 a = *(const float4*)(wsrc + kq * 4);
            float4 hi = make_float4(tf32rn(a.x), tf32rn(a.y), tf32rn(a.z), tf32rn(a.w));
            int f4 = (kq >> 3) * 1024 + row * 8 + ((kq & 7) ^ (row & 7));
            *(float4*)(sm + VG_BH + f4 * 4) = hi;
        }
    }
    __syncthreads();

    // phase 2: 1-term mma
    int wi = (wid & 3) * 32, wn = (wid >> 2) * 64;
    float acc[2][8][4];
#pragma unroll
    for (int mt = 0; mt < 2; ++mt)
#pragma unroll
        for (int nt = 0; nt < 8; ++nt)
#pragma unroll
            for (int r = 0; r < 4; ++r) acc[mt][nt][r] = 0.f;

#pragma unroll
    for (int k8 = 0; k8 < 8; ++k8) {
        int kb = k8 * 8;
        int sec = (kb >> 5) * 4096;
        int kl = kb & 31;
        uint32_t ah[2][4];
#pragma unroll
        for (int mt = 0; mt < 2; ++mt) {
            int r0 = wi + mt * 16 + g;
            ah[mt][0] = __float_as_uint(sm[VG_AH + sec + fidx32(r0, kl + tg)]);
            ah[mt][1] = __float_as_uint(sm[VG_AH + sec + fidx32(r0 + 8, kl + tg)]);
            ah[mt][2] = __float_as_uint(sm[VG_AH + sec + fidx32(r0, kl + 4 + tg)]);
            ah[mt][3] = __float_as_uint(sm[VG_AH + sec + fidx32(r0 + 8, kl + 4 + tg)]);
        }
#pragma unroll
        for (int nt = 0; nt < 8; ++nt) {
            int n0 = wn + nt * 8 + g;
            uint32_t b0 = __float_as_uint(sm[VG_BH + sec + fidx32(n0, kl + tg)]);
            uint32_t b1 = __float_as_uint(sm[VG_BH + sec + fidx32(n0, kl + 4 + tg)]);
#pragma unroll
            for (int mt = 0; mt < 2; ++mt)
                mma_tf32(acc[mt][nt], ah[mt], b0, b1);
        }
    }
    __syncthreads();

    // phase 3: epilogue
    float* Cs = sm;
    float* Cg2 = sm + 8448;
#pragma unroll
    for (int mt = 0; mt < 2; ++mt) {
        int r = wi + mt * 16 + g;
#pragma unroll
        for (int nt = 0; nt < 8; ++nt) {
            int col = wn + nt * 8 + 2 * tg;
            if (wid < 4) {
                Cs[col * 132 + r]            = acc[mt][nt][0];
                Cs[(col + 1) * 132 + r]      = acc[mt][nt][1];
                Cs[col * 132 + r + 8]        = acc[mt][nt][2];
                Cs[(col + 1) * 132 + r + 8]  = acc[mt][nt][3];
            } else {
                int cl = col - 64;
                Cg2[cl * 132 + r]            = 1.0f / (1.0f + __expf(-acc[mt][nt][0]));
                Cg2[(cl + 1) * 132 + r]      = 1.0f / (1.0f + __expf(-acc[mt][nt][1]));
                Cg2[cl * 132 + r + 8]        = 1.0f / (1.0f + __expf(-acc[mt][nt][2]));
                Cg2[(cl + 1) * 132 + r + 8]  = 1.0f / (1.0f + __expf(-acc[mt][nt][3]));
            }
        }
    }
    __syncthreads();
#pragma unroll
    for (int it = 0; it < 16; ++it) {
        int u = it * 256 + tid;
        int c = u >> 6, rem = u & 63;
        int jgl = rem >> 2, j3 = rem & 3;
        int sl = jgl * 8 + j3;
        float v0 = tf32rn(Cs[c * 132 + sl]);
        float v1 = tf32rn(Cs[c * 132 + sl + 4]);
        int d = c & 7, hh = c >> 3;
        int ndg = d * 64 + (n >> 3);
        int gpos = n & 7;
        size_t off = (((size_t)hh * 512 + ndg) * 64 + (size_t)((s0 >> 3) + jgl)) * 64
                   + (gpos * 4 + j3) * 2;
        *(float2*)(g_vTf + off) = make_float2(v0, v1);
    }
#pragma unroll
    for (int it = 0; it < 8; ++it) {
        int idx = it * 256 + tid;
        int c = idx >> 5, sq = idx & 31;
        *(float4*)(g_gT + ((size_t)c * 512 + n) * 512 + s0 + sq * 4) =
            *(const float4*)(Cg2 + c * 132 + sq * 4);
    }
}

// ---------------------------------------------------------------------------
// Kernel 4: pwa 1-term TF32 mma GEMM, 3-stage cp.async, gate in epilogue.
// (exact R9 version — measured 139us)
// Block 512 thr: M=256(i) x N=128(nd), K=512, kc=32.
// Stage (floats): A 8192 | B 4096 = 48KB; 3 stages = 144KB.
// ---------------------------------------------------------------------------
#define PW_STGF 12288
#define PW_STGB 49152
#define PW_SMEMB (3 * PW_STGB)

__device__ __forceinline__ void pw_ldstage(uint32_t sb, int tid,
                                           const float* Ah_g, const float* Bg,
                                           int chunk)
{
    int jg0 = chunk * 4;
#pragma unroll
    for (int it = 0; it < 4; ++it) {       // A: 2048 float4
        int t = it * 512 + tid;
        int Igl = t >> 7, rem = t & 127;
        int jgl = rem >> 5, part = rem & 31;
        size_t src = (size_t)Igl * 65536 + (jg0 + jgl) * 128 + part * 4;
        CP_ASYNC16(sb + (uint32_t)t * 16, Ah_g + src);
    }
#pragma unroll
    for (int it = 0; it < 2; ++it) {       // B: 1024 float4
        int t = it * 512 + tid;
        int ndgl = t >> 6, rem = t & 63;
        int jgl = rem >> 4, part = rem & 15;
        size_t src = (size_t)ndgl * 4096 + (jg0 + jgl) * 64 + part * 4;
        CP_ASYNC16(sb + 32768 + (uint32_t)t * 16, Bg + src);
    }
}

__global__ __launch_bounds__(512, 1) void pwa_mma_kernel()
{
    extern __shared__ float sm[];
    uint32_t sbase = smem_u32(sm);
    int tid = threadIdx.x, wid = tid >> 5, lane = tid & 31;
    int g = lane >> 2, tg = lane & 3;
    int h = blockIdx.z;
    int i0 = blockIdx.y * 256;
    int nd0 = blockIdx.x * 128;
    const float* Ah_g = g_whf + (size_t)((i0 >> 4) * 8 + h) * 8192;
    const float* Bg   = g_vTf + (size_t)(h * 512 + (nd0 >> 3)) * 4096;

    int iw = (wid & 3) * 4;
    int nw = (wid >> 2) * 4;
    int wi = (wid & 3) * 64, wn = (wid >> 2) * 32;

    float acc[4][4][4];
#pragma unroll
    for (int mt = 0; mt < 4; ++mt)
#pragma unroll
        for (int nt = 0; nt < 4; ++nt)
#pragma unroll
            for (int r = 0; r < 4; ++r) acc[mt][nt][r] = 0.f;

    pw_ldstage(sbase, tid, Ah_g, Bg, 0);
    CP_COMMIT();
    pw_ldstage(sbase + PW_STGB, tid, Ah_g, Bg, 1);
    CP_COMMIT();

    for (int c = 0; c < 16; ++c) {
        int slot = c % 3;
        if (c + 2 < 16) {
            pw_ldstage(sbase + ((c + 2) % 3) * PW_STGB, tid, Ah_g, Bg, c + 2);
            CP_COMMIT();
            CP_WAIT(2);
        } else if (c + 1 < 16) {
            CP_WAIT(1);
        } else {
            CP_WAIT(0);
        }
        __syncthreads();

        const float* Ah = sm + slot * PW_STGF;
        const float* Bh = Ah + 8192;
#pragma unroll
        for (int kk = 0; kk < 4; ++kk) {
            float4 ahv[4];
#pragma unroll
            for (int mt = 0; mt < 4; ++mt) {
                int blk = ((iw + mt) * 4 + kk) * 128 + lane * 4;
                ahv[mt] = *(const float4*)(Ah + blk);
            }
#pragma unroll
            for (int nt = 0; nt < 4; ++nt) {
                float2 bv = *(const float2*)(Bh + ((nw + nt) * 4 + kk) * 64 + lane * 2);
                uint32_t b0 = __float_as_uint(bv.x);
                uint32_t b1 = __float_as_uint(bv.y);
#pragma unroll
                for (int mt = 0; mt < 4; ++mt)
                    mma_tf32(acc[mt][nt], (const uint32_t*)&ahv[mt], b0, b1);
            }
        }
        __syncthreads();
    }

    // epilogue: stage C [col 128][260 rows], gate-multiply, coalesced store
    float* Cs = sm;
#pragma unroll
    for (int mt = 0; mt < 4; ++mt) {
        int r = wi + mt * 16 + g;
#pragma unroll
        for (int nt = 0; nt < 4; ++nt) {
            int col = wn + nt * 8 + 2 * tg;
            Cs[col * 260 + r]            = acc[mt][nt][0];
            Cs[(col + 1) * 260 + r]      = acc[mt][nt][1];
            Cs[col * 260 + r + 8]        = acc[mt][nt][2];
            Cs[(col + 1) * 260 + r + 8]  = acc[mt][nt][3];
        }
    }
    __syncthreads();
    size_t obase = ((size_t)h * 4096 + nd0) * 512 + i0;
#pragma unroll
    for (int it = 0; it < 16; ++it) {
        int idx = it * 512 + tid;
        int col = idx >> 6, rq = idx & 63;
        float4 ov = *(const float4*)(Cs + col * 260 + rq * 4);
        float4 gv = *(const float4*)(g_gT + obase + (size_t)col * 512 + rq * 4);
        ov.x *= gv.x; ov.y *= gv.y; ov.z *= gv.z; ov.w *= gv.w;
        *(float4*)(g_o2 + obase + (size_t)col * 512 + rq * 4) = ov;
    }
}

// ---------------------------------------------------------------------------
// Kernel 5: out = (gated o2) @ Wout^T  (exact R9/R8 FFMA version)
// ---------------------------------------------------------------------------
__global__ __launch_bounds__(256) void out_kernel(
    const float* __restrict__ Wout, float* __restrict__ out)
{
    __shared__ float As[64 * 128];
    __shared__ float Wt[64 * 64];
    int tid = threadIdx.x;
    int n = blockIdx.x & 511, s0 = (blockIdx.x >> 9) * 128;

#pragma unroll
    for (int it = 0; it < 4; ++it) {
        int idx = it * 256 + tid;
        int c = idx & 63, kq = idx >> 6;
        float4 a = *(const float4*)(Wout + c * 64 + kq * 4);
        Wt[(kq * 4 + 0) * 64 + c] = a.x;
        Wt[(kq * 4 + 1) * 64 + c] = a.y;
        Wt[(kq * 4 + 2) * 64 + c] = a.z;
        Wt[(kq * 4 + 3) * 64 + c] = a.w;
    }

#pragma unroll
    for (int it = 0; it < 8; ++it) {
        int idx = it * 256 + tid;
        int c = idx >> 5, sq = idx & 31;
        *(float4*)(As + c * 128 + sq * 4) =
            *(const float4*)(g_o2 + ((size_t)c * 512 + n) * 512 + s0 + sq * 4);
    }
    __syncthreads();

    int tx = tid & 15, ty = tid >> 4;
    float acc[8][4];
#pragma unroll
    for (int r = 0; r < 8; ++r)
#pragma unroll
        for (int c = 0; c < 4; ++c) acc[r][c] = 0.f;

#pragma unroll
    for (int k = 0; k < 64; ++k) {
        float4 a0 = *(const float4*)(As + k * 128 + ty * 4);
        float4 a1 = *(const float4*)(As + k * 128 + 64 + ty * 4);
        float4 w = *(const float4*)(Wt + k * 64 + tx * 4);
        float a[8] = {a0.x, a0.y, a0.z, a0.w, a1.x, a1.y, a1.z, a1.w};
        float wr[4] = {w.x, w.y, w.z, w.w};
#pragma unroll
        for (int r = 0; r < 8; ++r)
#pragma unroll
            for (int c = 0; c < 4; ++c)
                acc[r][c] = fmaf(a[r], wr[c], acc[r][c]);
    }
#pragma unroll
    for (int rh = 0; rh < 2; ++rh)
#pragma unroll
        for (int rr = 0; rr < 4; ++rr) {
            int orow = rh * 64 + ty * 4 + rr;
            float4 v4 = make_float4(acc[rh * 4 + rr][0], acc[rh * 4 + rr][1],
                                    acc[rh * 4 + rr][2], acc[rh * 4 + rr][3]);
            *(float4*)(out + ((size_t)(s0 + orow) * 512 + n) * CM + tx * 4) = v4;
        }
}

// ---------------------------------------------------------------------------
extern "C" void kernel_launch(void* const* d_in, const int* in_sizes, int n_in,
                              void* d_out, int out_size)
{
    const float* m    = (const float*)d_in[0];
    const float* z    = (const float*)d_in[1];
    const float* lnmw = (const float*)d_in[2];
    const float* lnmb = (const float*)d_in[3];
    const float* lnzw = (const float*)d_in[4];
    const float* lnzb = (const float*)d_in[5];
    const float* Wv   = (const float*)d_in[6];
    const float* Wb   = (const float*)d_in[7];
    const float* Wg   = (const float*)d_in[8];
    const float* Wout = (const float*)d_in[9];
    float* out = (float*)d_out;

    cudaFuncSetAttribute(pwa_mma_kernel,
                         cudaFuncAttributeMaxDynamicSharedMemorySize, PW_SMEMB);
    cudaFuncSetAttribute(vg_kernel,
                         cudaFuncAttributeMaxDynamicSharedMemorySize, VG_SMEMB);
    cudaFuncSetAttribute(softmax_kernel,
                         cudaFuncAttributeMaxDynamicSharedMemorySize, SMX_SMEMB);

    bias_ln_kernel<<<SQ * SQ / 64, 256>>>(z, lnzw, lnzb, Wb);
    softmax_kernel<<<(SQ / 16) * NH, 256, SMX_SMEMB>>>();
    vg_kernel<<<dim3(512, 4), 256, VG_SMEMB>>>(m, lnmw, lnmb, Wv, Wg);
    dim3 gD(32, 2, NH);
    pwa_mma_kernel<<<gD, 512, PW_SMEMB>>>();
    out_kernel<<<SQ * NSEQ / 128, 256>>>(Wout, out);
}

// round 12
// speedup vs baseline: 1.4338x; 1.0220x over previous
#include <cuda_runtime.h>
#include <cuda_fp16.h>
#include <cstdint>

#define SQ 512
#define NSEQ 512
#define CM 64
#define CZ 128
#define NH 8
#define EPS 1e-5f

// Scratch (device globals: allocation-free)
__device__ float g_w[(size_t)SQ * NH * SQ];        // raw logits [i][h][j]
__device__ float g_whf[(size_t)SQ * NH * SQ];      // w hi, A-frag layout [I][h][jg][lane][4]
__device__ float g_vTf[(size_t)CM * NSEQ * SQ];    // v, B-frag layout [h][ndg][jg][lane][2]
__device__ __half g_gTh[(size_t)CM * NSEQ * SQ];   // gate fp16 [(c*512+n)*512 + s]
__device__ __half g_o2h[(size_t)CM * NSEQ * SQ];   // gated o fp16 [(c*512+n)*512 + i]

__device__ __forceinline__ float warp_sum(float v) {
#pragma unroll
    for (int o = 16; o > 0; o >>= 1) v += __shfl_xor_sync(0xffffffffu, v, o);
    return v;
}
__device__ __forceinline__ uint32_t smem_u32(const void* p) {
    uint32_t a;
    asm("{ .reg .u64 t; cvta.to.shared.u64 t, %1; cvt.u32.u64 %0, t; }" : "=r"(a) : "l"(p));
    return a;
}
__device__ __forceinline__ float tf32rn(float x) {
    uint32_t r;
    asm("cvt.rna.tf32.f32 %0, %1;" : "=r"(r) : "f"(x));
    return __uint_as_float(r);
}
__device__ __forceinline__ void mma_tf32(float* d, const uint32_t* a,
                                         uint32_t b0, uint32_t b1) {
    asm volatile(
        "mma.sync.aligned.m16n8k8.row.col.f32.tf32.tf32.f32 "
        "{%0,%1,%2,%3}, {%4,%5,%6,%7}, {%8,%9}, {%0,%1,%2,%3};"
        : "+f"(d[0]), "+f"(d[1]), "+f"(d[2]), "+f"(d[3])
        : "r"(a[0]), "r"(a[1]), "r"(a[2]), "r"(a[3]), "r"(b0), "r"(b1));
}
#define CP_ASYNC16(dst, src) \
    asm volatile("cp.async.cg.shared.global [%0], [%1], 16;" :: "r"(dst), "l"(src))
#define CP_COMMIT() asm volatile("cp.async.commit_group;")
#define CP_WAIT(n)  asm volatile("cp.async.wait_group %0;" :: "n"(n))

// swizzled float index (used by vg phase-2 only)
__device__ __forceinline__ int fidx32(int row, int k) {
    return row * 32 + ((((k >> 2) ^ (row & 7)) << 2) | (k & 3));
}

// ---------------------------------------------------------------------------
// Kernel 1: b[i,h,j] = LN(z[i,j,:]) . W_b[h,:] -> g_w.  (R8 version, proven)
// ---------------------------------------------------------------------------
__global__ __launch_bounds__(256) void bias_ln_kernel(
    const float* __restrict__ z, const float* __restrict__ lnw,
    const float* __restrict__ lnb, const float* __restrict__ Wb)
{
    __shared__ float zn[64 * 132];
    __shared__ float swb[8 * 132];
    __shared__ float bs[2 * 64 * 8];
    int tid = threadIdx.x, wid = tid >> 5, lane = tid & 31;
    int g = lane >> 2, tg = lane & 3;

    {
        int h = tid >> 5;
        *(float4*)(swb + h * 132 + lane * 4) = *(const float4*)(Wb + h * CZ + lane * 4);
    }
    float4 lw = *(const float4*)(lnw + lane * 4);
    float4 lb = *(const float4*)(lnb + lane * 4);

    size_t R0 = (size_t)blockIdx.x * 64;
#pragma unroll
    for (int rr = 0; rr < 8; ++rr) {
        int row = wid * 8 + rr;
        float4 x = *(const float4*)(z + (R0 + row) * CZ + lane * 4);
        float s = warp_sum(x.x + x.y + x.z + x.w);
        float mu = s * (1.0f / CZ);
        float d0 = x.x - mu, d1 = x.y - mu, d2 = x.z - mu, d3 = x.w - mu;
        float q = warp_sum(d0 * d0 + d1 * d1 + d2 * d2 + d3 * d3);
        float rs = rsqrtf(q * (1.0f / CZ) + EPS);
        float4 nv;
        nv.x = d0 * rs * lw.x + lb.x;
        nv.y = d1 * rs * lw.y + lb.y;
        nv.z = d2 * rs * lw.z + lb.z;
        nv.w = d3 * rs * lw.w + lb.w;
        *(float4*)(zn + row * 132 + lane * 4) = nv;
    }
    __syncthreads();

    {
        int wmt = wid & 3, kh = wid >> 2;
        float acc[4] = {0.f, 0.f, 0.f, 0.f};
#pragma unroll
        for (int ks = 0; ks < 8; ++ks) {
            int k = kh * 64 + ks * 8;
            float a0 = zn[(wmt * 16 + g) * 132 + k + tg];
            float a1 = zn[(wmt * 16 + g + 8) * 132 + k + tg];
            float a2 = zn[(wmt * 16 + g) * 132 + k + tg + 4];
            float a3 = zn[(wmt * 16 + g + 8) * 132 + k + tg + 4];
            uint32_t ah[4], al[4];
            float h0 = tf32rn(a0), h1 = tf32rn(a1), h2 = tf32rn(a2), h3 = tf32rn(a3);
            ah[0] = __float_as_uint(h0); ah[1] = __float_as_uint(h1);
            ah[2] = __float_as_uint(h2); ah[3] = __float_as_uint(h3);
            al[0] = __float_as_uint(tf32rn(a0 - h0));
            al[1] = __float_as_uint(tf32rn(a1 - h1));
            al[2] = __float_as_uint(tf32rn(a2 - h2));
            al[3] = __float_as_uint(tf32rn(a3 - h3));
            float b0 = swb[g * 132 + k + tg];
            float b1 = swb[g * 132 + k + tg + 4];
            float bh0 = tf32rn(b0), bh1 = tf32rn(b1);
            uint32_t ubh0 = __float_as_uint(bh0), ubh1 = __float_as_uint(bh1);
            uint32_t ubl0 = __float_as_uint(tf32rn(b0 - bh0));
            uint32_t ubl1 = __float_as_uint(tf32rn(b1 - bh1));
            mma_tf32(acc, ah, ubh0, ubh1);
            mma_tf32(acc, al, ubh0, ubh1);
            mma_tf32(acc, ah, ubl0, ubl1);
        }
        int base = kh * 512 + (wmt * 16 + g) * 8 + 2 * tg;
        bs[base] = acc[0];
        bs[base + 1] = acc[1];
        bs[base + 64] = acc[2];
        bs[base + 65] = acc[3];
    }
    __syncthreads();
    {
        int h = tid >> 6, row = tid & 63;
        float v = bs[row * 8 + h] + bs[512 + row * 8 + h];
        float v2 = bs[row * 8 + h + 4] + bs[512 + row * 8 + h + 4];
        int i = (int)(R0 >> 9), j0 = (int)(R0 & 511);
        g_w[(size_t)i * 4096 + h * 512 + j0 + row] = v;
        g_w[(size_t)i * 4096 + (h + 4) * 512 + j0 + row] = v2;
    }
}

// ---------------------------------------------------------------------------
// Kernel 2: softmax over j; emits A-fragment-layout hi slab only.
// ---------------------------------------------------------------------------
#define SMX_SMEMB (8704 * 4)
__global__ __launch_bounds__(256, 1) void softmax_kernel()
{
    extern __shared__ float sx[];
    float* smh = sx;
    int tid = threadIdx.x;
    int row = tid >> 4, l = tid & 15;
    int I = blockIdx.x >> 3, h = blockIdx.x & 7;
    const float* src = g_w + ((size_t)(I * 16 + row)) * 4096 + h * 512;

    float w[32];
    float mx = -1e30f;
#pragma unroll
    for (int jj = 0; jj < 32; ++jj) {
        w[jj] = src[jj * 16 + l];
        mx = fmaxf(mx, w[jj]);
    }
#pragma unroll
    for (int o = 8; o > 0; o >>= 1) mx = fmaxf(mx, __shfl_xor_sync(0xffffffffu, mx, o));
    float sum = 0.f;
#pragma unroll
    for (int jj = 0; jj < 32; ++jj) {
        w[jj] = __expf(w[jj] - mx);
        sum += w[jj];
    }
#pragma unroll
    for (int o = 8; o > 0; o >>= 1) sum += __shfl_xor_sync(0xffffffffu, sum, o);
    float inv = 1.0f / sum;
#pragma unroll
    for (int jj = 0; jj < 32; ++jj) {
        int j = jj * 16 + l;
        smh[j * 17 + row] = tf32rn(w[jj] * inv);
    }
    __syncthreads();

    float* dh = g_whf + (size_t)(I * 8 + h) * 8192;
#pragma unroll
    for (int it = 0; it < 8; ++it) {
        int u = it * 256 + tid;
        int jg = u >> 5, lane = u & 31;
        float4 vh;
#pragma unroll
        for (int idx = 0; idx < 4; ++idx) {
            int il = (lane >> 2) + (idx & 1) * 8;
            int j = jg * 8 + ((idx >> 1) & 1) * 4 + (lane & 3);
            (&vh.x)[idx] = smh[j * 17 + il];
        }
        *(float4*)(dh + u * 4) = vh;
    }
}

// ---------------------------------------------------------------------------
// Kernel 3: fused LN(m) -> 1-term mma -> vT (B-frag layout) + gate (fp16).
// ---------------------------------------------------------------------------
#define VG_AH 0
#define VG_BH 8192
#define VG_SMEMB (16896 * 4)

__global__ __launch_bounds__(256, 1) void vg_kernel(
    const float* __restrict__ m, const float* __restrict__ lnw,
    const float* __restrict__ lnb, const float* __restrict__ Wv,
    const float* __restrict__ Wg)
{
    extern __shared__ float sm[];
    int tid = threadIdx.x, wid = tid >> 5, lane = tid & 31;
    int g = lane >> 2, tg = lane & 3;
    int n = blockIdx.x, s0 = blockIdx.y * 128;

    {   // phase 1: LN + tf32 round to swizzled smem (hi only)
        int row = tid >> 1, half = tid & 1;
        const float* src = m + ((size_t)(s0 + row) * 512 + n) * CM + half * 32;
        float v[32];
        float s = 0.f, q = 0.f;
#pragma unroll
        for (int qd = 0; qd < 8; ++qd) {
            float4 a = *(const float4*)(src + qd * 4);
            v[qd * 4 + 0] = a.x; v[qd * 4 + 1] = a.y;
            v[qd * 4 + 2] = a.z; v[qd * 4 + 3] = a.w;
            s += a.x + a.y + a.z + a.w;
            q += a.x * a.x + a.y * a.y + a.z * a.z + a.w * a.w;
        }
        s += __shfl_xor_sync(0xffffffffu, s, 1);
        q += __shfl_xor_sync(0xffffffffu, q, 1);
        float mu = s * (1.0f / CM);
        float var = q * (1.0f / CM) - mu * mu;
        float rs = rsqrtf(var + EPS);
#pragma unroll
        for (int qd = 0; qd < 8; ++qd) {
            int kq = half * 8 + qd;
            float xs[4];
#pragma unroll
            for (int t = 0; t < 4; ++t) {
                int k = kq * 4 + t;
                xs[t] = (v[qd * 4 + t] - mu) * rs * __ldg(lnw + k) + __ldg(lnb + k);
            }
            float4 hi = make_float4(tf32rn(xs[0]), tf32rn(xs[1]), tf32rn(xs[2]), tf32rn(xs[3]));
            int f4 = (kq >> 3) * 1024 + row * 8 + ((kq & 7) ^ (row & 7));
            *(float4*)(sm + VG_AH + f4 * 4) = hi;
        }
        const float* wsrc = (row < 64) ? (Wv + row * 64) : (Wg + (row - 64) * 64);
#pragma unroll
        for (int qd = 0; qd < 8; ++qd) {
            int kq = half * 8 + qd;
            float4 a = *(const float4*)(wsrc + kq * 4);
            float4 hi = make_float4(tf32rn(a.x), tf32rn(a.y), tf32rn(a.z), tf32rn(a.w));
            int f4 = (kq >> 3) * 1024 + row * 8 + ((kq & 7) ^ (row & 7));
            *(float4*)(sm + VG_BH + f4 * 4) = hi;
        }
    }
    __syncthreads();

    // phase 2: 1-term mma
    int wi = (wid & 3) * 32, wn = (wid >> 2) * 64;
    float acc[2][8][4];
#pragma unroll
    for (int mt = 0; mt < 2; ++mt)
#pragma unroll
        for (int nt = 0; nt < 8; ++nt)
#pragma unroll
            for (int r = 0; r < 4; ++r) acc[mt][nt][r] = 0.f;

#pragma unroll
    for (int k8 = 0; k8 < 8; ++k8) {
        int kb = k8 * 8;
        int sec = (kb >> 5) * 4096;
        int kl = kb & 31;
        uint32_t ah[2][4];
#pragma unroll
        for (int mt = 0; mt < 2; ++mt) {
            int r0 = wi + mt * 16 + g;
            ah[mt][0] = __float_as_uint(sm[VG_AH + sec + fidx32(r0, kl + tg)]);
            ah[mt][1] = __float_as_uint(sm[VG_AH + sec + fidx32(r0 + 8, kl + tg)]);
            ah[mt][2] = __float_as_uint(sm[VG_AH + sec + fidx32(r0, kl + 4 + tg)]);
            ah[mt][3] = __float_as_uint(sm[VG_AH + sec + fidx32(r0 + 8, kl + 4 + tg)]);
        }
#pragma unroll
        for (int nt = 0; nt < 8; ++nt) {
            int n0 = wn + nt * 8 + g;
            uint32_t b0 = __float_as_uint(sm[VG_BH + sec + fidx32(n0, kl + tg)]);
            uint32_t b1 = __float_as_uint(sm[VG_BH + sec + fidx32(n0, kl + 4 + tg)]);
#pragma unroll
            for (int mt = 0; mt < 2; ++mt)
                mma_tf32(acc[mt][nt], ah[mt], b0, b1);
        }
    }
    __syncthreads();

    // phase 3: epilogue
    float* Cs = sm;
    float* Cg2 = sm + 8448;
#pragma unroll
    for (int mt = 0; mt < 2; ++mt) {
        int r = wi + mt * 16 + g;
#pragma unroll
        for (int nt = 0; nt < 8; ++nt) {
            int col = wn + nt * 8 + 2 * tg;
            if (wid < 4) {
                Cs[col * 132 + r]            = acc[mt][nt][0];
                Cs[(col + 1) * 132 + r]      = acc[mt][nt][1];
                Cs[col * 132 + r + 8]        = acc[mt][nt][2];
                Cs[(col + 1) * 132 + r + 8]  = acc[mt][nt][3];
            } else {
                int cl = col - 64;
                Cg2[cl * 132 + r]            = 1.0f / (1.0f + __expf(-acc[mt][nt][0]));
                Cg2[(cl + 1) * 132 + r]      = 1.0f / (1.0f + __expf(-acc[mt][nt][1]));
                Cg2[cl * 132 + r + 8]        = 1.0f / (1.0f + __expf(-acc[mt][nt][2]));
                Cg2[(cl + 1) * 132 + r + 8]  = 1.0f / (1.0f + __expf(-acc[mt][nt][3]));
            }
        }
    }
    __syncthreads();
#pragma unroll
    for (int it = 0; it < 16; ++it) {
        int u = it * 256 + tid;
        int c = u >> 6, rem = u & 63;
        int jgl = rem >> 2, j3 = rem & 3;
        int sl = jgl * 8 + j3;
        float v0 = tf32rn(Cs[c * 132 + sl]);
        float v1 = tf32rn(Cs[c * 132 + sl + 4]);
        int d = c & 7, hh = c >> 3;
        int ndg = d * 64 + (n >> 3);
        int gpos = n & 7;
        size_t off = (((size_t)hh * 512 + ndg) * 64 + (size_t)((s0 >> 3) + jgl)) * 64
                   + (gpos * 4 + j3) * 2;
        *(float2*)(g_vTf + off) = make_float2(v0, v1);
    }
    // gate -> fp16, [(c*512+n)*512 + s], 8 halves (16B) per thread-iter
#pragma unroll
    for (int it = 0; it < 4; ++it) {
        int idx = it * 256 + tid;
        int c = idx >> 4, s8 = (idx & 15) * 8;
        float4 a = *(const float4*)(Cg2 + c * 132 + s8);
        float4 b = *(const float4*)(Cg2 + c * 132 + s8 + 4);
        __half2 hs[4];
        hs[0] = __floats2half2_rn(a.x, a.y);
        hs[1] = __floats2half2_rn(a.z, a.w);
        hs[2] = __floats2half2_rn(b.x, b.y);
        hs[3] = __floats2half2_rn(b.z, b.w);
        *(uint4*)(g_gTh + ((size_t)c * 512 + n) * 512 + s0 + s8) = *(uint4*)hs;
    }
}

// ---------------------------------------------------------------------------
// Kernel 4: pwa 1-term TF32 mma GEMM, 3-stage cp.async, fp16 gate/o2 epilogue.
// Block 512 thr: M=256(i) x N=128(nd), K=512, kc=32.
// ---------------------------------------------------------------------------
#define PW_STGF 12288
#define PW_STGB 49152
#define PW_SMEMB (3 * PW_STGB)

__device__ __forceinline__ void pw_ldstage(uint32_t sb, int tid,
                                           const float* Ah_g, const float* Bg,
                                           int chunk)
{
    int jg0 = chunk * 4;
#pragma unroll
    for (int it = 0; it < 4; ++it) {       // A: 2048 float4
        int t = it * 512 + tid;
        int Igl = t >> 7, rem = t & 127;
        int jgl = rem >> 5, part = rem & 31;
        size_t src = (size_t)Igl * 65536 + (jg0 + jgl) * 128 + part * 4;
        CP_ASYNC16(sb + (uint32_t)t * 16, Ah_g + src);
    }
#pragma unroll
    for (int it = 0; it < 2; ++it) {       // B: 1024 float4
        int t = it * 512 + tid;
        int ndgl = t >> 6, rem = t & 63;
        int jgl = rem >> 4, part = rem & 15;
        size_t src = (size_t)ndgl * 4096 + (jg0 + jgl) * 64 + part * 4;
        CP_ASYNC16(sb + 32768 + (uint32_t)t * 16, Bg + src);
    }
}

__global__ __launch_bounds__(512, 1) void pwa_mma_kernel()
{
    extern __shared__ float sm[];
    uint32_t sbase = smem_u32(sm);
    int tid = threadIdx.x, wid = tid >> 5, lane = tid & 31;
    int g = lane >> 2, tg = lane & 3;
    int h = blockIdx.z;
    int i0 = blockIdx.y * 256;
    int nd0 = blockIdx.x * 128;
    const float* Ah_g = g_whf + (size_t)((i0 >> 4) * 8 + h) * 8192;
    const float* Bg   = g_vTf + (size_t)(h * 512 + (nd0 >> 3)) * 4096;

    int iw = (wid & 3) * 4;
    int nw = (wid >> 2) * 4;
    int wi = (wid & 3) * 64, wn = (wid >> 2) * 32;

    float acc[4][4][4];
#pragma unroll
    for (int mt = 0; mt < 4; ++mt)
#pragma unroll
        for (int nt = 0; nt < 4; ++nt)
#pragma unroll
            for (int r = 0; r < 4; ++r) acc[mt][nt][r] = 0.f;

    pw_ldstage(sbase, tid, Ah_g, Bg, 0);
    CP_COMMIT();
    pw_ldstage(sbase + PW_STGB, tid, Ah_g, Bg, 1);
    CP_COMMIT();

    for (int c = 0; c < 16; ++c) {
        int slot = c % 3;
        if (c + 2 < 16) {
            pw_ldstage(sbase + ((c + 2) % 3) * PW_STGB, tid, Ah_g, Bg, c + 2);
            CP_COMMIT();
            CP_WAIT(2);
        } else if (c + 1 < 16) {
            CP_WAIT(1);
        } else {
            CP_WAIT(0);
        }
        __syncthreads();

        const float* Ah = sm + slot * PW_STGF;
        const float* Bh = Ah + 8192;
#pragma unroll
        for (int kk = 0; kk < 4; ++kk) {
            float4 ahv[4];
#pragma unroll
            for (int mt = 0; mt < 4; ++mt) {
                int blk = ((iw + mt) * 4 + kk) * 128 + lane * 4;
                ahv[mt] = *(const float4*)(Ah + blk);
            }
#pragma unroll
            for (int nt = 0; nt < 4; ++nt) {
                float2 bv = *(const float2*)(Bh + ((nw + nt) * 4 + kk) * 64 + lane * 2);
                uint32_t b0 = __float_as_uint(bv.x);
                uint32_t b1 = __float_as_uint(bv.y);
#pragma unroll
                for (int mt = 0; mt < 4; ++mt)
                    mma_tf32(acc[mt][nt], (const uint32_t*)&ahv[mt], b0, b1);
            }
        }
        __syncthreads();
    }

    // epilogue: stage C [col 128][260 rows], fp16 gate-multiply, fp16 store
    float* Cs = sm;
#pragma unroll
    for (int mt = 0; mt < 4; ++mt) {
        int r = wi + mt * 16 + g;
#pragma unroll
        for (int nt = 0; nt < 4; ++nt) {
            int col = wn + nt * 8 + 2 * tg;
            Cs[col * 260 + r]            = acc[mt][nt][0];
            Cs[(col + 1) * 260 + r]      = acc[mt][nt][1];
            Cs[col * 260 + r + 8]        = acc[mt][nt][2];
            Cs[(col + 1) * 260 + r + 8]  = acc[mt][nt][3];
        }
    }
    __syncthreads();
    size_t obase = ((size_t)h * 4096 + nd0) * 512 + i0;
#pragma unroll
    for (int it = 0; it < 16; ++it) {
        int idx = it * 512 + tid;
        int col = idx >> 6, rq = idx & 63;
        float4 ov = *(const float4*)(Cs + col * 260 + rq * 4);
        const __half2* gp = (const __half2*)(g_gTh + obase + (size_t)col * 512 + rq * 4);
        float2 g0 = __half22float2(gp[0]);
        float2 g1 = __half22float2(gp[1]);
        __half2 r0 = __floats2half2_rn(ov.x * g0.x, ov.y * g0.y);
        __half2 r1 = __floats2half2_rn(ov.z * g1.x, ov.w * g1.y);
        uint2 pk;
        pk.x = *(uint32_t*)&r0;
        pk.y = *(uint32_t*)&r1;
        *(uint2*)(g_o2h + obase + (size_t)col * 512 + rq * 4) = pk;
    }
}

// ---------------------------------------------------------------------------
// Kernel 5: out = (gated o2, fp16) @ Wout^T
// ---------------------------------------------------------------------------
__global__ __launch_bounds__(256) void out_kernel(
    const float* __restrict__ Wout, float* __restrict__ out)
{
    __shared__ float As[64 * 128];
    __shared__ float Wt[64 * 64];
    int tid = threadIdx.x;
    int n = blockIdx.x & 511, s0 = (blockIdx.x >> 9) * 128;

#pragma unroll
    for (int it = 0; it < 4; ++it) {
        int idx = it * 256 + tid;
        int c = idx & 63, kq = idx >> 6;
        float4 a = *(const float4*)(Wout + c * 64 + kq * 4);
        Wt[(kq * 4 + 0) * 64 + c] = a.x;
        Wt[(kq * 4 + 1) * 64 + c] = a.y;
        Wt[(kq * 4 + 2) * 64 + c] = a.z;
        Wt[(kq * 4 + 3) * 64 + c] = a.w;
    }

#pragma unroll
    for (int it = 0; it < 8; ++it) {
        int idx = it * 256 + tid;
        int c = idx >> 5, sq = idx & 31;
        const __half2* op = (const __half2*)(g_o2h + ((size_t)c * 512 + n) * 512 + s0 + sq * 4);
        float2 f0 = __half22float2(op[0]);
        float2 f1 = __half22float2(op[1]);
        *(float4*)(As + c * 128 + sq * 4) = make_float4(f0.x, f0.y, f1.x, f1.y);
    }
    __syncthreads();

    int tx = tid & 15, ty = tid >> 4;
    float acc[8][4];
#pragma unroll
    for (int r = 0; r < 8; ++r)
#pragma unroll
        for (int c = 0; c < 4; ++c) acc[r][c] = 0.f;

#pragma unroll
    for (int k = 0; k < 64; ++k) {
        float4 a0 = *(const float4*)(As + k * 128 + ty * 4);
        float4 a1 = *(const float4*)(As + k * 128 + 64 + ty * 4);
        float4 w = *(const float4*)(Wt + k * 64 + tx * 4);
        float a[8] = {a0.x, a0.y, a0.z, a0.w, a1.x, a1.y, a1.z, a1.w};
        float wr[4] = {w.x, w.y, w.z, w.w};
#pragma unroll
        for (int r = 0; r < 8; ++r)
#pragma unroll
            for (int c = 0; c < 4; ++c)
                acc[r][c] = fmaf(a[r], wr[c], acc[r][c]);
    }
#pragma unroll
    for (int rh = 0; rh < 2; ++rh)
#pragma unroll
        for (int rr = 0; rr < 4; ++rr) {
            int orow = rh * 64 + ty * 4 + rr;
            float4 v4 = make_float4(acc[rh * 4 + rr][0], acc[rh * 4 + rr][1],
                                    acc[rh * 4 + rr][2], acc[rh * 4 + rr][3]);
            *(float4*)(out + ((size_t)(s0 + orow) * 512 + n) * CM + tx * 4) = v4;
        }
}

// ---------------------------------------------------------------------------
extern "C" void kernel_launch(void* const* d_in, const int* in_sizes, int n_in,
                              void* d_out, int out_size)
{
    const float* m    = (const float*)d_in[0];
    const float* z    = (const float*)d_in[1];
    const float* lnmw = (const float*)d_in[2];
    const float* lnmb = (const float*)d_in[3];
    const float* lnzw = (const float*)d_in[4];
    const float* lnzb = (const float*)d_in[5];
    const float* Wv   = (const float*)d_in[6];
    const float* Wb   = (const float*)d_in[7];
    const float* Wg   = (const float*)d_in[8];
    const float* Wout = (const float*)d_in[9];
    float* out = (float*)d_out;

    cudaFuncSetAttribute(pwa_mma_kernel,
                         cudaFuncAttributeMaxDynamicSharedMemorySize, PW_SMEMB);
    cudaFuncSetAttribute(vg_kernel,
                         cudaFuncAttributeMaxDynamicSharedMemorySize, VG_SMEMB);
    cudaFuncSetAttribute(softmax_kernel,
                         cudaFuncAttributeMaxDynamicSharedMemorySize, SMX_SMEMB);

    bias_ln_kernel<<<SQ * SQ / 64, 256>>>(z, lnzw, lnzb, Wb);
    softmax_kernel<<<(SQ / 16) * NH, 256, SMX_SMEMB>>>();
    vg_kernel<<<dim3(512, 4), 256, VG_SMEMB>>>(m, lnmw, lnmb, Wv, Wg);
    dim3 gD(32, 2, NH);
    pwa_mma_kernel<<<gD, 512, PW_SMEMB>>>();
    out_kernel<<<SQ * NSEQ / 128, 256>>>(Wout, out);
}

// round 13
// speedup vs baseline: 1.7145x; 1.1958x over previous
#include <cuda_runtime.h>
#include <cuda_fp16.h>
#include <cstdint>

#define SQ 512
#define NSEQ 512
#define CM 64
#define CZ 128
#define NH 8
#define EPS 1e-5f

// Scratch (device globals: allocation-free)
__device__ float  g_w[(size_t)SQ * NH * SQ];       // raw logits [i][h][j]
__device__ __half g_whf[(size_t)SQ * NH * SQ];     // w fp16, m16n8k16 A-frag [I][h][jg16][lane][4reg][2]
__device__ __half g_vTf[(size_t)CM * NSEQ * SQ];   // v fp16, m16n8k16 B-frag [h][ndg][jg16][lane][2reg][2]
__device__ __half g_gTh[(size_t)CM * NSEQ * SQ];   // gate fp16 [(c*512+n)*512 + s]
__device__ __half g_o2h[(size_t)CM * NSEQ * SQ];   // gated o fp16 [(c*512+n)*512 + i]

__device__ __forceinline__ float warp_sum(float v) {
#pragma unroll
    for (int o = 16; o > 0; o >>= 1) v += __shfl_xor_sync(0xffffffffu, v, o);
    return v;
}
__device__ __forceinline__ uint32_t smem_u32(const void* p) {
    uint32_t a;
    asm("{ .reg .u64 t; cvta.to.shared.u64 t, %1; cvt.u32.u64 %0, t; }" : "=r"(a) : "l"(p));
    return a;
}
__device__ __forceinline__ float tf32rn(float x) {
    uint32_t r;
    asm("cvt.rna.tf32.f32 %0, %1;" : "=r"(r) : "f"(x));
    return __uint_as_float(r);
}
__device__ __forceinline__ void mma_tf32(float* d, const uint32_t* a,
                                         uint32_t b0, uint32_t b1) {
    asm volatile(
        "mma.sync.aligned.m16n8k8.row.col.f32.tf32.tf32.f32 "
        "{%0,%1,%2,%3}, {%4,%5,%6,%7}, {%8,%9}, {%0,%1,%2,%3};"
        : "+f"(d[0]), "+f"(d[1]), "+f"(d[2]), "+f"(d[3])
        : "r"(a[0]), "r"(a[1]), "r"(a[2]), "r"(a[3]), "r"(b0), "r"(b1));
}
__device__ __forceinline__ void mma_f16(float* d, const uint32_t* a,
                                        uint32_t b0, uint32_t b1) {
    asm volatile(
        "mma.sync.aligned.m16n8k16.row.col.f32.f16.f16.f32 "
        "{%0,%1,%2,%3}, {%4,%5,%6,%7}, {%8,%9}, {%0,%1,%2,%3};"
        : "+f"(d[0]), "+f"(d[1]), "+f"(d[2]), "+f"(d[3])
        : "r"(a[0]), "r"(a[1]), "r"(a[2]), "r"(a[3]), "r"(b0), "r"(b1));
}
#define CP_ASYNC16(dst, src) \
    asm volatile("cp.async.cg.shared.global [%0], [%1], 16;" :: "r"(dst), "l"(src))
#define CP_COMMIT() asm volatile("cp.async.commit_group;")
#define CP_WAIT(n)  asm volatile("cp.async.wait_group %0;" :: "n"(n))

// swizzled float index (used by vg phase-2 only)
__device__ __forceinline__ int fidx32(int row, int k) {
    return row * 32 + ((((k >> 2) ^ (row & 7)) << 2) | (k & 3));
}

// ---------------------------------------------------------------------------
// Kernel 1: b[i,h,j] = LN(z[i,j,:]) . W_b[h,:] -> g_w.  (R8 version, proven)
// ---------------------------------------------------------------------------
__global__ __launch_bounds__(256) void bias_ln_kernel(
    const float* __restrict__ z, const float* __restrict__ lnw,
    const float* __restrict__ lnb, const float* __restrict__ Wb)
{
    __shared__ float zn[64 * 132];
    __shared__ float swb[8 * 132];
    __shared__ float bs[2 * 64 * 8];
    int tid = threadIdx.x, wid = tid >> 5, lane = tid & 31;
    int g = lane >> 2, tg = lane & 3;

    {
        int h = tid >> 5;
        *(float4*)(swb + h * 132 + lane * 4) = *(const float4*)(Wb + h * CZ + lane * 4);
    }
    float4 lw = *(const float4*)(lnw + lane * 4);
    float4 lb = *(const float4*)(lnb + lane * 4);

    size_t R0 = (size_t)blockIdx.x * 64;
#pragma unroll
    for (int rr = 0; rr < 8; ++rr) {
        int row = wid * 8 + rr;
        float4 x = *(const float4*)(z + (R0 + row) * CZ + lane * 4);
        float s = warp_sum(x.x + x.y + x.z + x.w);
        float mu = s * (1.0f / CZ);
        float d0 = x.x - mu, d1 = x.y - mu, d2 = x.z - mu, d3 = x.w - mu;
        float q = warp_sum(d0 * d0 + d1 * d1 + d2 * d2 + d3 * d3);
        float rs = rsqrtf(q * (1.0f / CZ) + EPS);
        float4 nv;
        nv.x = d0 * rs * lw.x + lb.x;
        nv.y = d1 * rs * lw.y + lb.y;
        nv.z = d2 * rs * lw.z + lb.z;
        nv.w = d3 * rs * lw.w + lb.w;
        *(float4*)(zn + row * 132 + lane * 4) = nv;
    }
    __syncthreads();

    {
        int wmt = wid & 3, kh = wid >> 2;
        float acc[4] = {0.f, 0.f, 0.f, 0.f};
#pragma unroll
        for (int ks = 0; ks < 8; ++ks) {
            int k = kh * 64 + ks * 8;
            float a0 = zn[(wmt * 16 + g) * 132 + k + tg];
            float a1 = zn[(wmt * 16 + g + 8) * 132 + k + tg];
            float a2 = zn[(wmt * 16 + g) * 132 + k + tg + 4];
            float a3 = zn[(wmt * 16 + g + 8) * 132 + k + tg + 4];
            uint32_t ah[4], al[4];
            float h0 = tf32rn(a0), h1 = tf32rn(a1), h2 = tf32rn(a2), h3 = tf32rn(a3);
            ah[0] = __float_as_uint(h0); ah[1] = __float_as_uint(h1);
            ah[2] = __float_as_uint(h2); ah[3] = __float_as_uint(h3);
            al[0] = __float_as_uint(tf32rn(a0 - h0));
            al[1] = __float_as_uint(tf32rn(a1 - h1));
            al[2] = __float_as_uint(tf32rn(a2 - h2));
            al[3] = __float_as_uint(tf32rn(a3 - h3));
            float b0 = swb[g * 132 + k + tg];
            float b1 = swb[g * 132 + k + tg + 4];
            float bh0 = tf32rn(b0), bh1 = tf32rn(b1);
            uint32_t ubh0 = __float_as_uint(bh0), ubh1 = __float_as_uint(bh1);
            uint32_t ubl0 = __float_as_uint(tf32rn(b0 - bh0));
            uint32_t ubl1 = __float_as_uint(tf32rn(b1 - bh1));
            mma_tf32(acc, ah, ubh0, ubh1);
            mma_tf32(acc, al, ubh0, ubh1);
            mma_tf32(acc, ah, ubl0, ubl1);
        }
        int base = kh * 512 + (wmt * 16 + g) * 8 + 2 * tg;
        bs[base] = acc[0];
        bs[base + 1] = acc[1];
        bs[base + 64] = acc[2];
        bs[base + 65] = acc[3];
    }
    __syncthreads();
    {
        int h = tid >> 6, row = tid & 63;
        float v = bs[row * 8 + h] + bs[512 + row * 8 + h];
        float v2 = bs[row * 8 + h + 4] + bs[512 + row * 8 + h + 4];
        int i = (int)(R0 >> 9), j0 = (int)(R0 & 511);
        g_w[(size_t)i * 4096 + h * 512 + j0 + row] = v;
        g_w[(size_t)i * 4096 + (h + 4) * 512 + j0 + row] = v2;
    }
}

// ---------------------------------------------------------------------------
// Kernel 2: softmax over j; emits fp16 m16n8k16 A-fragment slabs.
// ---------------------------------------------------------------------------
#define SMX_SMEMB (8704 * 4)
__global__ __launch_bounds__(256, 1) void softmax_kernel()
{
    extern __shared__ float sx[];
    float* smh = sx;            // [j*17 + i_loc], fp32 weights
    int tid = threadIdx.x;
    int row = tid >> 4, l = tid & 15;
    int I = blockIdx.x >> 3, h = blockIdx.x & 7;
    const float* src = g_w + ((size_t)(I * 16 + row)) * 4096 + h * 512;

    float w[32];
    float mx = -1e30f;
#pragma unroll
    for (int jj = 0; jj < 32; ++jj) {
        w[jj] = src[jj * 16 + l];
        mx = fmaxf(mx, w[jj]);
    }
#pragma unroll
    for (int o = 8; o > 0; o >>= 1) mx = fmaxf(mx, __shfl_xor_sync(0xffffffffu, mx, o));
    float sum = 0.f;
#pragma unroll
    for (int jj = 0; jj < 32; ++jj) {
        w[jj] = __expf(w[jj] - mx);
        sum += w[jj];
    }
#pragma unroll
    for (int o = 8; o > 0; o >>= 1) sum += __shfl_xor_sync(0xffffffffu, sum, o);
    float inv = 1.0f / sum;
#pragma unroll
    for (int jj = 0; jj < 32; ++jj) {
        int j = jj * 16 + l;
        smh[j * 17 + row] = w[jj] * inv;
    }
    __syncthreads();

    // emit fp16 A-frag: per (jg16, lane): 4 regs x 2 halves
    // reg r: i_loc = g + (r&1)*8 ; j = jg16*16 + (r>>1)*8 + 2*tg + half
    __half* dh = g_whf + (size_t)(I * 8 + h) * 8192;
#pragma unroll
    for (int it = 0; it < 4; ++it) {
        int u = it * 256 + tid;
        int jg16 = u >> 5, lane = u & 31;
        int gg = lane >> 2, tt = lane & 3;
        __half2 hs[4];
#pragma unroll
        for (int r = 0; r < 4; ++r) {
            int il = gg + (r & 1) * 8;
            int j0 = jg16 * 16 + ((r >> 1) * 8) + 2 * tt;
            hs[r] = __floats2half2_rn(smh[j0 * 17 + il], smh[(j0 + 1) * 17 + il]);
        }
        *(uint4*)(dh + (size_t)u * 8) = *(uint4*)hs;
    }
}

// ---------------------------------------------------------------------------
// Kernel 3: fused LN(m) -> 1-term mma -> vT (fp16 B-frag) + gate (fp16).
// ---------------------------------------------------------------------------
#define VG_AH 0
#define VG_BH 8192
#define VG_SMEMB (16896 * 4)

__global__ __launch_bounds__(256, 1) void vg_kernel(
    const float* __restrict__ m, const float* __restrict__ lnw,
    const float* __restrict__ lnb, const float* __restrict__ Wv,
    const float* __restrict__ Wg)
{
    extern __shared__ float sm[];
    int tid = threadIdx.x, wid = tid >> 5, lane = tid & 31;
    int g = lane >> 2, tg = lane & 3;
    int n = blockIdx.x, s0 = blockIdx.y * 128;

    {   // phase 1: LN + tf32 round to swizzled smem (hi only)
        int row = tid >> 1, half = tid & 1;
        const float* src = m + ((size_t)(s0 + row) * 512 + n) * CM + half * 32;
        float v[32];
        float s = 0.f, q = 0.f;
#pragma unroll
        for (int qd = 0; qd < 8; ++qd) {
            float4 a = *(const float4*)(src + qd * 4);
            v[qd * 4 + 0] = a.x; v[qd * 4 + 1] = a.y;
            v[qd * 4 + 2] = a.z; v[qd * 4 + 3] = a.w;
            s += a.x + a.y + a.z + a.w;
            q += a.x * a.x + a.y * a.y + a.z * a.z + a.w * a.w;
        }
        s += __shfl_xor_sync(0xffffffffu, s, 1);
        q += __shfl_xor_sync(0xffffffffu, q, 1);
        float mu = s * (1.0f / CM);
        float var = q * (1.0f / CM) - mu * mu;
        float rs = rsqrtf(var + EPS);
#pragma unroll
        for (int qd = 0; qd < 8; ++qd) {
            int kq = half * 8 + qd;
            float xs[4];
#pragma unroll
            for (int t = 0; t < 4; ++t) {
                int k = kq * 4 + t;
                xs[t] = (v[qd * 4 + t] - mu) * rs * __ldg(lnw + k) + __ldg(lnb + k);
            }
            float4 hi = make_float4(tf32rn(xs[0]), tf32rn(xs[1]), tf32rn(xs[2]), tf32rn(xs[3]));
            int f4 = (kq >> 3) * 1024 + row * 8 + ((kq & 7) ^ (row & 7));
            *(float4*)(sm + VG_AH + f4 * 4) = hi;
        }
        const float* wsrc = (row < 64) ? (Wv + row * 64) : (Wg + (row - 64) * 64);
#pragma unroll
        for (int qd = 0; qd < 8; ++qd) {
            int kq = half * 8 + qd;
            float4 a = *(const float4*)(wsrc + kq * 4);
            float4 hi = make_float4(tf32rn(a.x), tf32rn(a.y), tf32rn(a.z), tf32rn(a.w));
            int f4 = (kq >> 3) * 1024 + row * 8 + ((kq & 7) ^ (row & 7));
            *(float4*)(sm + VG_BH + f4 * 4) = hi;
        }
    }
    __syncthreads();

    // phase 2: 1-term mma
    int wi = (wid & 3) * 32, wn = (wid >> 2) * 64;
    float acc[2][8][4];
#pragma unroll
    for (int mt = 0; mt < 2; ++mt)
#pragma unroll
        for (int nt = 0; nt < 8; ++nt)
#pragma unroll
            for (int r = 0; r < 4; ++r) acc[mt][nt][r] = 0.f;

#pragma unroll
    for (int k8 = 0; k8 < 8; ++k8) {
        int kb = k8 * 8;
        int sec = (kb >> 5) * 4096;
        int kl = kb & 31;
        uint32_t ah[2][4];
#pragma unroll
        for (int mt = 0; mt < 2; ++mt) {
            int r0 = wi + mt * 16 + g;
            ah[mt][0] = __float_as_uint(sm[VG_AH + sec + fidx32(r0, kl + tg)]);
            ah[mt][1] = __float_as_uint(sm[VG_AH + sec + fidx32(r0 + 8, kl + tg)]);
            ah[mt][2] = __float_as_uint(sm[VG_AH + sec + fidx32(r0, kl + 4 + tg)]);
            ah[mt][3] = __float_as_uint(sm[VG_AH + sec + fidx32(r0 + 8, kl + 4 + tg)]);
        }
#pragma unroll
        for (int nt = 0; nt < 8; ++nt) {
            int n0 = wn + nt * 8 + g;
            uint32_t b0 = __float_as_uint(sm[VG_BH + sec + fidx32(n0, kl + tg)]);
            uint32_t b1 = __float_as_uint(sm[VG_BH + sec + fidx32(n0, kl + 4 + tg)]);
#pragma unroll
            for (int mt = 0; mt < 2; ++mt)
                mma_tf32(acc[mt][nt], ah[mt], b0, b1);
        }
    }
    __syncthreads();

    // phase 3: epilogue
    float* Cs = sm;
    float* Cg2 = sm + 8448;
#pragma unroll
    for (int mt = 0; mt < 2; ++mt) {
        int r = wi + mt * 16 + g;
#pragma unroll
        for (int nt = 0; nt < 8; ++nt) {
            int col = wn + nt * 8 + 2 * tg;
            if (wid < 4) {
                Cs[col * 132 + r]            = acc[mt][nt][0];
                Cs[(col + 1) * 132 + r]      = acc[mt][nt][1];
                Cs[col * 132 + r + 8]        = acc[mt][nt][2];
                Cs[(col + 1) * 132 + r + 8]  = acc[mt][nt][3];
            } else {
                int cl = col - 64;
                Cg2[cl * 132 + r]            = 1.0f / (1.0f + __expf(-acc[mt][nt][0]));
                Cg2[(cl + 1) * 132 + r]      = 1.0f / (1.0f + __expf(-acc[mt][nt][1]));
                Cg2[cl * 132 + r + 8]        = 1.0f / (1.0f + __expf(-acc[mt][nt][2]));
                Cg2[(cl + 1) * 132 + r + 8]  = 1.0f / (1.0f + __expf(-acc[mt][nt][3]));
            }
        }
    }
    __syncthreads();
    // vT -> fp16 B-frag: nd = d*512+n; ndg = d*64+(n>>3); lane = (n&7)*4+tg
    // thread writes 4 halves: k = jg16*16 + {2tg, 2tg+1, 2tg+8, 2tg+9}
#pragma unroll
    for (int it = 0; it < 8; ++it) {
        int u = it * 256 + tid;
        int c = u >> 5, rem = u & 31;
        int jgl16 = rem >> 2, tt = rem & 3;
        int sl0 = jgl16 * 16 + 2 * tt;
        __half2 p0 = __floats2half2_rn(Cs[c * 132 + sl0], Cs[c * 132 + sl0 + 1]);
        __half2 p1 = __floats2half2_rn(Cs[c * 132 + sl0 + 8], Cs[c * 132 + sl0 + 9]);
        int d = c & 7, hh = c >> 3;
        int ndg = d * 64 + (n >> 3);
        int gpos = n & 7;
        size_t off = ((size_t)hh * 512 + ndg) * 4096
                   + (size_t)((s0 >> 4) + jgl16) * 128 + (gpos * 4 + tt) * 4;
        uint2 pk;
        pk.x = *(uint32_t*)&p0;
        pk.y = *(uint32_t*)&p1;
        *(uint2*)(g_vTf + off) = pk;
    }
    // gate -> fp16, [(c*512+n)*512 + s]
#pragma unroll
    for (int it = 0; it < 4; ++it) {
        int idx = it * 256 + tid;
        int c = idx >> 4, s8 = (idx & 15) * 8;
        float4 a = *(const float4*)(Cg2 + c * 132 + s8);
        float4 b = *(const float4*)(Cg2 + c * 132 + s8 + 4);
        __half2 hs[4];
        hs[0] = __floats2half2_rn(a.x, a.y);
        hs[1] = __floats2half2_rn(a.z, a.w);
        hs[2] = __floats2half2_rn(b.x, b.y);
        hs[3] = __floats2half2_rn(b.z, b.w);
        *(uint4*)(g_gTh + ((size_t)c * 512 + n) * 512 + s0 + s8) = *(uint4*)hs;
    }
}

// ---------------------------------------------------------------------------
// Kernel 4: pwa fp16 m16n8k16 mma GEMM, 3-stage cp.async, fp16 gate/o2.
// Block 512 thr: M=256(i) x N=128(nd), K=512, kc=32 (2 k16-steps/chunk).
// Stage (halves): A 8192 (16KB) | B 4096 (8KB) = 24KB; 3 stages = 72KB.
// Epilogue Cs needs 133120B -> smem size 133120.
// ---------------------------------------------------------------------------
#define PW_STGH 12288
#define PW_STGB 24576
#define PW_SMEMB 133120

__device__ __forceinline__ void pw_ldstage(uint32_t sb, int tid,
                                           const __half* Ah_g, const __half* Bg,
                                           int chunk)
{
    int jg0 = chunk * 2;        // jg16 base
#pragma unroll
    for (int it = 0; it < 2; ++it) {       // A: 1024 x 16B
        int t = it * 512 + tid;
        int Igl = t >> 6, rem = t & 63;
        int jgl = rem >> 5, lane = rem & 31;
        size_t src = (size_t)Igl * 65536 + (size_t)(jg0 + jgl) * 256 + lane * 8;
        CP_ASYNC16(sb + (uint32_t)t * 16, Ah_g + src);
    }
    {                                       // B: 512 x 16B
        int t = tid;
        int ndgl = t >> 5, rem = t & 31;
        int jgl = rem >> 4, lp = rem & 15;
        size_t src = (size_t)ndgl * 4096 + (size_t)(jg0 + jgl) * 128 + lp * 8;
        CP_ASYNC16(sb + 16384 + (uint32_t)t * 16, Bg + src);
    }
}

__global__ __launch_bounds__(512, 1) void pwa_mma_kernel()
{
    extern __shared__ float sm[];
    uint32_t sbase = smem_u32(sm);
    int tid = threadIdx.x, wid = tid >> 5, lane = tid & 31;
    int g = lane >> 2, tg = lane & 3;
    int h = blockIdx.z;
    int i0 = blockIdx.y * 256;
    int nd0 = blockIdx.x * 128;
    const __half* Ah_g = g_whf + (size_t)((i0 >> 4) * 8 + h) * 8192;
    const __half* Bg   = g_vTf + (size_t)(h * 512 + (nd0 >> 3)) * 4096;

    int iw = (wid & 3) * 4;
    int nw = (wid >> 2) * 4;
    int wi = (wid & 3) * 64, wn = (wid >> 2) * 32;

    float acc[4][4][4];
#pragma unroll
    for (int mt = 0; mt < 4; ++mt)
#pragma unroll
        for (int nt = 0; nt < 4; ++nt)
#pragma unroll
            for (int r = 0; r < 4; ++r) acc[mt][nt][r] = 0.f;

    pw_ldstage(sbase, tid, Ah_g, Bg, 0);
    CP_COMMIT();
    pw_ldstage(sbase + PW_STGB, tid, Ah_g, Bg, 1);
    CP_COMMIT();

    for (int c = 0; c < 16; ++c) {
        int slot = c % 3;
        if (c + 2 < 16) {
            pw_ldstage(sbase + ((c + 2) % 3) * PW_STGB, tid, Ah_g, Bg, c + 2);
            CP_COMMIT();
            CP_WAIT(2);
        } else if (c + 1 < 16) {
            CP_WAIT(1);
        } else {
            CP_WAIT(0);
        }
        __syncthreads();

        const __half* Ah2 = (const __half*)sm + (size_t)slot * PW_STGH;
        const __half* Bh2 = Ah2 + 8192;
#pragma unroll
        for (int kk = 0; kk < 2; ++kk) {
            uint4 av[4];
#pragma unroll
            for (int mt = 0; mt < 4; ++mt) {
                int Igl = iw + mt;
                av[mt] = *(const uint4*)(Ah2 + (size_t)((Igl * 2 + kk) * 32 + lane) * 8);
            }
#pragma unroll
            for (int nt = 0; nt < 4; ++nt) {
                int ndgl = nw + nt;
                uint2 bv = *(const uint2*)(Bh2 + (size_t)((ndgl * 2 + kk) * 32 + lane) * 4);
#pragma unroll
                for (int mt = 0; mt < 4; ++mt)
                    mma_f16(acc[mt][nt], (const uint32_t*)&av[mt], bv.x, bv.y);
            }
        }
        __syncthreads();
    }

    // epilogue: stage C [col 128][260 rows], fp16 gate-multiply, fp16 store
    float* Cs = sm;
#pragma unroll
    for (int mt = 0; mt < 4; ++mt) {
        int r = wi + mt * 16 + g;
#pragma unroll
        for (int nt = 0; nt < 4; ++nt) {
            int col = wn + nt * 8 + 2 * tg;
            Cs[col * 260 + r]            = acc[mt][nt][0];
            Cs[(col + 1) * 260 + r]      = acc[mt][nt][1];
            Cs[col * 260 + r + 8]        = acc[mt][nt][2];
            Cs[(col + 1) * 260 + r + 8]  = acc[mt][nt][3];
        }
    }
    __syncthreads();
    size_t obase = ((size_t)h * 4096 + nd0) * 512 + i0;
#pragma unroll
    for (int it = 0; it < 16; ++it) {
        int idx = it * 512 + tid;
        int col = idx >> 6, rq = idx & 63;
        float4 ov = *(const float4*)(Cs + col * 260 + rq * 4);
        const __half2* gp = (const __half2*)(g_gTh + obase + (size_t)col * 512 + rq * 4);
        float2 g0 = __half22float2(gp[0]);
        float2 g1 = __half22float2(gp[1]);
        __half2 r0 = __floats2half2_rn(ov.x * g0.x, ov.y * g0.y);
        __half2 r1 = __floats2half2_rn(ov.z * g1.x, ov.w * g1.y);
        uint2 pk;
        pk.x = *(uint32_t*)&r0;
        pk.y = *(uint32_t*)&r1;
        *(uint2*)(g_o2h + obase + (size_t)col * 512 + rq * 4) = pk;
    }
}

// ---------------------------------------------------------------------------
// Kernel 5: out = (gated o2, fp16) @ Wout^T
// ---------------------------------------------------------------------------
__global__ __launch_bounds__(256) void out_kernel(
    const float* __restrict__ Wout, float* __restrict__ out)
{
    __shared__ float As[64 * 128];
    __shared__ float Wt[64 * 64];
    int tid = threadIdx.x;
    int n = blockIdx.x & 511, s0 = (blockIdx.x >> 9) * 128;

#pragma unroll
    for (int it = 0; it < 4; ++it) {
        int idx = it * 256 + tid;
        int c = idx & 63, kq = idx >> 6;
        float4 a = *(const float4*)(Wout + c * 64 + kq * 4);
        Wt[(kq * 4 + 0) * 64 + c] = a.x;
        Wt[(kq * 4 + 1) * 64 + c] = a.y;
        Wt[(kq * 4 + 2) * 64 + c] = a.z;
        Wt[(kq * 4 + 3) * 64 + c] = a.w;
    }

#pragma unroll
    for (int it = 0; it < 8; ++it) {
        int idx = it * 256 + tid;
        int c = idx >> 5, sq = idx & 31;
        const __half2* op = (const __half2*)(g_o2h + ((size_t)c * 512 + n) * 512 + s0 + sq * 4);
        float2 f0 = __half22float2(op[0]);
        float2 f1 = __half22float2(op[1]);
        *(float4*)(As + c * 128 + sq * 4) = make_float4(f0.x, f0.y, f1.x, f1.y);
    }
    __syncthreads();

    int tx = tid & 15, ty = tid >> 4;
    float acc[8][4];
#pragma unroll
    for (int r = 0; r < 8; ++r)
#pragma unroll
        for (int c = 0; c < 4; ++c) acc[r][c] = 0.f;

#pragma unroll
    for (int k = 0; k < 64; ++k) {
        float4 a0 = *(const float4*)(As + k * 128 + ty * 4);
        float4 a1 = *(const float4*)(As + k * 128 + 64 + ty * 4);
        float4 w = *(const float4*)(Wt + k * 64 + tx * 4);
        float a[8] = {a0.x, a0.y, a0.z, a0.w, a1.x, a1.y, a1.z, a1.w};
        float wr[4] = {w.x, w.y, w.z, w.w};
#pragma unroll
        for (int r = 0; r < 8; ++r)
#pragma unroll
            for (int c = 0; c < 4; ++c)
                acc[r][c] = fmaf(a[r], wr[c], acc[r][c]);
    }
#pragma unroll
    for (int rh = 0; rh < 2; ++rh)
#pragma unroll
        for (int rr = 0; rr < 4; ++rr) {
            int orow = rh * 64 + ty * 4 + rr;
            float4 v4 = make_float4(acc[rh * 4 + rr][0], acc[rh * 4 + rr][1],
                                    acc[rh * 4 + rr][2], acc[rh * 4 + rr][3]);
            *(float4*)(out + ((size_t)(s0 + orow) * 512 + n) * CM + tx * 4) = v4;
        }
}

// ---------------------------------------------------------------------------
extern "C" void kernel_launch(void* const* d_in, const int* in_sizes, int n_in,
                              void* d_out, int out_size)
{
    const float* m    = (const float*)d_in[0];
    const float* z    = (const float*)d_in[1];
    const float* lnmw = (const float*)d_in[2];
    const float* lnmb = (const float*)d_in[3];
    const float* lnzw = (const float*)d_in[4];
    const float* lnzb = (const float*)d_in[5];
    const float* Wv   = (const float*)d_in[6];
    const float* Wb   = (const float*)d_in[7];
    const float* Wg   = (const float*)d_in[8];
    const float* Wout = (const float*)d_in[9];
    float* out = (float*)d_out;

    cudaFuncSetAttribute(pwa_mma_kernel,
                         cudaFuncAttributeMaxDynamicSharedMemorySize, PW_SMEMB);
    cudaFuncSetAttribute(vg_kernel,
                         cudaFuncAttributeMaxDynamicSharedMemorySize, VG_SMEMB);
    cudaFuncSetAttribute(softmax_kernel,
                         cudaFuncAttributeMaxDynamicSharedMemorySize, SMX_SMEMB);

    bias_ln_kernel<<<SQ * SQ / 64, 256>>>(z, lnzw, lnzb, Wb);
    softmax_kernel<<<(SQ / 16) * NH, 256, SMX_SMEMB>>>();
    vg_kernel<<<dim3(512, 4), 256, VG_SMEMB>>>(m, lnmw, lnmb, Wv, Wg);
    dim3 gD(32, 2, NH);
    pwa_mma_kernel<<<gD, 512, PW_SMEMB>>>();
    out_kernel<<<SQ * NSEQ / 128, 256>>>(Wout, out);
}

// round 14
// speedup vs baseline: 1.8715x; 1.0915x over previous
#include <cuda_runtime.h>
#include <cuda_fp16.h>
#include <cstdint>

#define SQ 512
#define NSEQ 512
#define CM 64
#define CZ 128
#define NH 8
#define EPS 1e-5f

// Scratch (device globals: allocation-free)
__device__ float  g_w[(size_t)SQ * NH * SQ];       // raw logits [i][h][j]
__device__ __half g_whf[(size_t)SQ * NH * SQ];     // w fp16, m16n8k16 A-frag
__device__ __half g_vTf[(size_t)CM * NSEQ * SQ];   // v fp16, m16n8k16 B-frag
__device__ __half g_gTh[(size_t)CM * NSEQ * SQ];   // gate fp16 [(c*512+n)*512 + s]
__device__ __half g_o2h[(size_t)CM * NSEQ * SQ];   // gated o fp16 [(c*512+n)*512 + i]

__device__ __forceinline__ float warp_sum(float v) {
#pragma unroll
    for (int o = 16; o > 0; o >>= 1) v += __shfl_xor_sync(0xffffffffu, v, o);
    return v;
}
__device__ __forceinline__ uint32_t smem_u32(const void* p) {
    uint32_t a;
    asm("{ .reg .u64 t; cvta.to.shared.u64 t, %1; cvt.u32.u64 %0, t; }" : "=r"(a) : "l"(p));
    return a;
}
__device__ __forceinline__ float tf32rn(float x) {
    uint32_t r;
    asm("cvt.rna.tf32.f32 %0, %1;" : "=r"(r) : "f"(x));
    return __uint_as_float(r);
}
__device__ __forceinline__ void mma_tf32(float* d, const uint32_t* a,
                                         uint32_t b0, uint32_t b1) {
    asm volatile(
        "mma.sync.aligned.m16n8k8.row.col.f32.tf32.tf32.f32 "
        "{%0,%1,%2,%3}, {%4,%5,%6,%7}, {%8,%9}, {%0,%1,%2,%3};"
        : "+f"(d[0]), "+f"(d[1]), "+f"(d[2]), "+f"(d[3])
        : "r"(a[0]), "r"(a[1]), "r"(a[2]), "r"(a[3]), "r"(b0), "r"(b1));
}
__device__ __forceinline__ void mma_f16(float* d, const uint32_t* a,
                                        uint32_t b0, uint32_t b1) {
    asm volatile(
        "mma.sync.aligned.m16n8k16.row.col.f32.f16.f16.f32 "
        "{%0,%1,%2,%3}, {%4,%5,%6,%7}, {%8,%9}, {%0,%1,%2,%3};"
        : "+f"(d[0]), "+f"(d[1]), "+f"(d[2]), "+f"(d[3])
        : "r"(a[0]), "r"(a[1]), "r"(a[2]), "r"(a[3]), "r"(b0), "r"(b1));
}
#define CP_ASYNC16(dst, src) \
    asm volatile("cp.async.cg.shared.global [%0], [%1], 16;" :: "r"(dst), "l"(src))
#define CP_COMMIT() asm volatile("cp.async.commit_group;")
#define CP_WAIT(n)  asm volatile("cp.async.wait_group %0;" :: "n"(n))

__device__ __forceinline__ int fidx32(int row, int k) {
    return row * 32 + ((((k >> 2) ^ (row & 7)) << 2) | (k & 3));
}

// ---------------------------------------------------------------------------
// Kernel 1: b[i,h,j] = LN(z[i,j,:]) . W_b[h,:] -> g_w.  (unchanged)
// ---------------------------------------------------------------------------
__global__ __launch_bounds__(256) void bias_ln_kernel(
    const float* __restrict__ z, const float* __restrict__ lnw,
    const float* __restrict__ lnb, const float* __restrict__ Wb)
{
    __shared__ float zn[64 * 132];
    __shared__ float swb[8 * 132];
    __shared__ float bs[2 * 64 * 8];
    int tid = threadIdx.x, wid = tid >> 5, lane = tid & 31;
    int g = lane >> 2, tg = lane & 3;

    {
        int h = tid >> 5;
        *(float4*)(swb + h * 132 + lane * 4) = *(const float4*)(Wb + h * CZ + lane * 4);
    }
    float4 lw = *(const float4*)(lnw + lane * 4);
    float4 lb = *(const float4*)(lnb + lane * 4);

    size_t R0 = (size_t)blockIdx.x * 64;
#pragma unroll
    for (int rr = 0; rr < 8; ++rr) {
        int row = wid * 8 + rr;
        float4 x = *(const float4*)(z + (R0 + row) * CZ + lane * 4);
        float s = warp_sum(x.x + x.y + x.z + x.w);
        float mu = s * (1.0f / CZ);
        float d0 = x.x - mu, d1 = x.y - mu, d2 = x.z - mu, d3 = x.w - mu;
        float q = warp_sum(d0 * d0 + d1 * d1 + d2 * d2 + d3 * d3);
        float rs = rsqrtf(q * (1.0f / CZ) + EPS);
        float4 nv;
        nv.x = d0 * rs * lw.x + lb.x;
        nv.y = d1 * rs * lw.y + lb.y;
        nv.z = d2 * rs * lw.z + lb.z;
        nv.w = d3 * rs * lw.w + lb.w;
        *(float4*)(zn + row * 132 + lane * 4) = nv;
    }
    __syncthreads();

    {
        int wmt = wid & 3, kh = wid >> 2;
        float acc[4] = {0.f, 0.f, 0.f, 0.f};
#pragma unroll
        for (int ks = 0; ks < 8; ++ks) {
            int k = kh * 64 + ks * 8;
            float a0 = zn[(wmt * 16 + g) * 132 + k + tg];
            float a1 = zn[(wmt * 16 + g + 8) * 132 + k + tg];
            float a2 = zn[(wmt * 16 + g) * 132 + k + tg + 4];
            float a3 = zn[(wmt * 16 + g + 8) * 132 + k + tg + 4];
            uint32_t ah[4], al[4];
            float h0 = tf32rn(a0), h1 = tf32rn(a1), h2 = tf32rn(a2), h3 = tf32rn(a3);
            ah[0] = __float_as_uint(h0); ah[1] = __float_as_uint(h1);
            ah[2] = __float_as_uint(h2); ah[3] = __float_as_uint(h3);
            al[0] = __float_as_uint(tf32rn(a0 - h0));
            al[1] = __float_as_uint(tf32rn(a1 - h1));
            al[2] = __float_as_uint(tf32rn(a2 - h2));
            al[3] = __float_as_uint(tf32rn(a3 - h3));
            float b0 = swb[g * 132 + k + tg];
            float b1 = swb[g * 132 + k + tg + 4];
            float bh0 = tf32rn(b0), bh1 = tf32rn(b1);
            uint32_t ubh0 = __float_as_uint(bh0), ubh1 = __float_as_uint(bh1);
            uint32_t ubl0 = __float_as_uint(tf32rn(b0 - bh0));
            uint32_t ubl1 = __float_as_uint(tf32rn(b1 - bh1));
            mma_tf32(acc, ah, ubh0, ubh1);
            mma_tf32(acc, al, ubh0, ubh1);
            mma_tf32(acc, ah, ubl0, ubl1);
        }
        int base = kh * 512 + (wmt * 16 + g) * 8 + 2 * tg;
        bs[base] = acc[0];
        bs[base + 1] = acc[1];
        bs[base + 64] = acc[2];
        bs[base + 65] = acc[3];
    }
    __syncthreads();
    {
        int h = tid >> 6, row = tid & 63;
        float v = bs[row * 8 + h] + bs[512 + row * 8 + h];
        float v2 = bs[row * 8 + h + 4] + bs[512 + row * 8 + h + 4];
        int i = (int)(R0 >> 9), j0 = (int)(R0 & 511);
        g_w[(size_t)i * 4096 + h * 512 + j0 + row] = v;
        g_w[(size_t)i * 4096 + (h + 4) * 512 + j0 + row] = v2;
    }
}

// ---------------------------------------------------------------------------
// Kernel 2: softmax over j; fp16 A-frag slabs.  (occ 2)
// ---------------------------------------------------------------------------
#define SMX_SMEMB (8704 * 4)
__global__ __launch_bounds__(256, 2) void softmax_kernel()
{
    extern __shared__ float sx[];
    float* smh = sx;
    int tid = threadIdx.x;
    int row = tid >> 4, l = tid & 15;
    int I = blockIdx.x >> 3, h = blockIdx.x & 7;
    const float* src = g_w + ((size_t)(I * 16 + row)) * 4096 + h * 512;

    float w[32];
    float mx = -1e30f;
#pragma unroll
    for (int jj = 0; jj < 32; ++jj) {
        w[jj] = src[jj * 16 + l];
        mx = fmaxf(mx, w[jj]);
    }
#pragma unroll
    for (int o = 8; o > 0; o >>= 1) mx = fmaxf(mx, __shfl_xor_sync(0xffffffffu, mx, o));
    float sum = 0.f;
#pragma unroll
    for (int jj = 0; jj < 32; ++jj) {
        w[jj] = __expf(w[jj] - mx);
        sum += w[jj];
    }
#pragma unroll
    for (int o = 8; o > 0; o >>= 1) sum += __shfl_xor_sync(0xffffffffu, sum, o);
    float inv = 1.0f / sum;
#pragma unroll
    for (int jj = 0; jj < 32; ++jj) {
        int j = jj * 16 + l;
        smh[j * 17 + row] = w[jj] * inv;
    }
    __syncthreads();

    __half* dh = g_whf + (size_t)(I * 8 + h) * 8192;
#pragma unroll
    for (int it = 0; it < 4; ++it) {
        int u = it * 256 + tid;
        int jg16 = u >> 5, lane = u & 31;
        int gg = lane >> 2, tt = lane & 3;
        __half2 hs[4];
#pragma unroll
        for (int r = 0; r < 4; ++r) {
            int il = gg + (r & 1) * 8;
            int j0 = jg16 * 16 + ((r >> 1) * 8) + 2 * tt;
            hs[r] = __floats2half2_rn(smh[j0 * 17 + il], smh[(j0 + 1) * 17 + il]);
        }
        *(uint4*)(dh + (size_t)u * 8) = *(uint4*)hs;
    }
}

// ---------------------------------------------------------------------------
// Kernel 3: fused LN(m) -> 1-term mma -> vT (fp16 B-frag) + gate (fp16). occ 2.
// ---------------------------------------------------------------------------
#define VG_AH 0
#define VG_BH 8192
#define VG_SMEMB (16896 * 4)

__global__ __launch_bounds__(256, 2) void vg_kernel(
    const float* __restrict__ m, const float* __restrict__ lnw,
    const float* __restrict__ lnb, const float* __restrict__ Wv,
    const float* __restrict__ Wg)
{
    extern __shared__ float sm[];
    int tid = threadIdx.x, wid = tid >> 5, lane = tid & 31;
    int g = lane >> 2, tg = lane & 3;
    int n = blockIdx.x, s0 = blockIdx.y * 128;

    {
        int row = tid >> 1, half = tid & 1;
        const float* src = m + ((size_t)(s0 + row) * 512 + n) * CM + half * 32;
        float v[32];
        float s = 0.f, q = 0.f;
#pragma unroll
        for (int qd = 0; qd < 8; ++qd) {
            float4 a = *(const float4*)(src + qd * 4);
            v[qd * 4 + 0] = a.x; v[qd * 4 + 1] = a.y;
            v[qd * 4 + 2] = a.z; v[qd * 4 + 3] = a.w;
            s += a.x + a.y + a.z + a.w;
            q += a.x * a.x + a.y * a.y + a.z * a.z + a.w * a.w;
        }
        s += __shfl_xor_sync(0xffffffffu, s, 1);
        q += __shfl_xor_sync(0xffffffffu, q, 1);
        float mu = s * (1.0f / CM);
        float var = q * (1.0f / CM) - mu * mu;
        float rs = rsqrtf(var + EPS);
#pragma unroll
        for (int qd = 0; qd < 8; ++qd) {
            int kq = half * 8 + qd;
            float xs[4];
#pragma unroll
            for (int t = 0; t < 4; ++t) {
                int k = kq * 4 + t;
                xs[t] = (v[qd * 4 + t] - mu) * rs * __ldg(lnw + k) + __ldg(lnb + k);
            }
            float4 hi = make_float4(tf32rn(xs[0]), tf32rn(xs[1]), tf32rn(xs[2]), tf32rn(xs[3]));
            int f4 = (kq >> 3) * 1024 + row * 8 + ((kq & 7) ^ (row & 7));
            *(float4*)(sm + VG_AH + f4 * 4) = hi;
        }
        const float* wsrc = (row < 64) ? (Wv + row * 64) : (Wg + (row - 64) * 64);
#pragma unroll
        for (int qd = 0; qd < 8; ++qd) {
            int kq = half * 8 + qd;
            float4 a = *(const float4*)(wsrc + kq * 4);
            float4 hi = make_float4(tf32rn(a.x), tf32rn(a.y), tf32rn(a.z), tf32rn(a.w));
            int f4 = (kq >> 3) * 1024 + row * 8 + ((kq & 7) ^ (row & 7));
            *(float4*)(sm + VG_BH + f4 * 4) = hi;
        }
    }
    __syncthreads();

    int wi = (wid & 3) * 32, wn = (wid >> 2) * 64;
    float acc[2][8][4];
#pragma unroll
    for (int mt = 0; mt < 2; ++mt)
#pragma unroll
        for (int nt = 0; nt < 8; ++nt)
#pragma unroll
            for (int r = 0; r < 4; ++r) acc[mt][nt][r] = 0.f;

#pragma unroll
    for (int k8 = 0; k8 < 8; ++k8) {
        int kb = k8 * 8;
        int sec = (kb >> 5) * 4096;
        int kl = kb & 31;
        uint32_t ah[2][4];
#pragma unroll
        for (int mt = 0; mt < 2; ++mt) {
            int r0 = wi + mt * 16 + g;
            ah[mt][0] = __float_as_uint(sm[VG_AH + sec + fidx32(r0, kl + tg)]);
            ah[mt][1] = __float_as_uint(sm[VG_AH + sec + fidx32(r0 + 8, kl + tg)]);
            ah[mt][2] = __float_as_uint(sm[VG_AH + sec + fidx32(r0, kl + 4 + tg)]);
            ah[mt][3] = __float_as_uint(sm[VG_AH + sec + fidx32(r0 + 8, kl + 4 + tg)]);
        }
#pragma unroll
        for (int nt = 0; nt < 8; ++nt) {
            int n0 = wn + nt * 8 + g;
            uint32_t b0 = __float_as_uint(sm[VG_BH + sec + fidx32(n0, kl + tg)]);
            uint32_t b1 = __float_as_uint(sm[VG_BH + sec + fidx32(n0, kl + 4 + tg)]);
#pragma unroll
            for (int mt = 0; mt < 2; ++mt)
                mma_tf32(acc[mt][nt], ah[mt], b0, b1);
        }
    }
    __syncthreads();

    float* Cs = sm;
    float* Cg2 = sm + 8448;
#pragma unroll
    for (int mt = 0; mt < 2; ++mt) {
        int r = wi + mt * 16 + g;
#pragma unroll
        for (int nt = 0; nt < 8; ++nt) {
            int col = wn + nt * 8 + 2 * tg;
            if (wid < 4) {
                Cs[col * 132 + r]            = acc[mt][nt][0];
                Cs[(col + 1) * 132 + r]      = acc[mt][nt][1];
                Cs[col * 132 + r + 8]        = acc[mt][nt][2];
                Cs[(col + 1) * 132 + r + 8]  = acc[mt][nt][3];
            } else {
                int cl = col - 64;
                Cg2[cl * 132 + r]            = 1.0f / (1.0f + __expf(-acc[mt][nt][0]));
                Cg2[(cl + 1) * 132 + r]      = 1.0f / (1.0f + __expf(-acc[mt][nt][1]));
                Cg2[cl * 132 + r + 8]        = 1.0f / (1.0f + __expf(-acc[mt][nt][2]));
                Cg2[(cl + 1) * 132 + r + 8]  = 1.0f / (1.0f + __expf(-acc[mt][nt][3]));
            }
        }
    }
    __syncthreads();
#pragma unroll
    for (int it = 0; it < 8; ++it) {
        int u = it * 256 + tid;
        int c = u >> 5, rem = u & 31;
        int jgl16 = rem >> 2, tt = rem & 3;
        int sl0 = jgl16 * 16 + 2 * tt;
        __half2 p0 = __floats2half2_rn(Cs[c * 132 + sl0], Cs[c * 132 + sl0 + 1]);
        __half2 p1 = __floats2half2_rn(Cs[c * 132 + sl0 + 8], Cs[c * 132 + sl0 + 9]);
        int d = c & 7, hh = c >> 3;
        int ndg = d * 64 + (n >> 3);
        int gpos = n & 7;
        size_t off = ((size_t)hh * 512 + ndg) * 4096
                   + (size_t)((s0 >> 4) + jgl16) * 128 + (gpos * 4 + tt) * 4;
        uint2 pk;
        pk.x = *(uint32_t*)&p0;
        pk.y = *(uint32_t*)&p1;
        *(uint2*)(g_vTf + off) = pk;
    }
#pragma unroll
    for (int it = 0; it < 4; ++it) {
        int idx = it * 256 + tid;
        int c = idx >> 4, s8 = (idx & 15) * 8;
        float4 a = *(const float4*)(Cg2 + c * 132 + s8);
        float4 b = *(const float4*)(Cg2 + c * 132 + s8 + 4);
        __half2 hs[4];
        hs[0] = __floats2half2_rn(a.x, a.y);
        hs[1] = __floats2half2_rn(a.z, a.w);
        hs[2] = __floats2half2_rn(b.x, b.y);
        hs[3] = __floats2half2_rn(b.z, b.w);
        *(uint4*)(g_gTh + ((size_t)c * 512 + n) * 512 + s0 + s8) = *(uint4*)hs;
    }
}

// ---------------------------------------------------------------------------
// Kernel 4: pwa fp16 m16n8k16 mma GEMM.  (exact R13 version — 79us)
// ---------------------------------------------------------------------------
#define PW_STGH 12288
#define PW_STGB 24576
#define PW_SMEMB 133120

__device__ __forceinline__ void pw_ldstage(uint32_t sb, int tid,
                                           const __half* Ah_g, const __half* Bg,
                                           int chunk)
{
    int jg0 = chunk * 2;
#pragma unroll
    for (int it = 0; it < 2; ++it) {
        int t = it * 512 + tid;
        int Igl = t >> 6, rem = t & 63;
        int jgl = rem >> 5, lane = rem & 31;
        size_t src = (size_t)Igl * 65536 + (size_t)(jg0 + jgl) * 256 + lane * 8;
        CP_ASYNC16(sb + (uint32_t)t * 16, Ah_g + src);
    }
    {
        int t = tid;
        int ndgl = t >> 5, rem = t & 31;
        int jgl = rem >> 4, lp = rem & 15;
        size_t src = (size_t)ndgl * 4096 + (size_t)(jg0 + jgl) * 128 + lp * 8;
        CP_ASYNC16(sb + 16384 + (uint32_t)t * 16, Bg + src);
    }
}

__global__ __launch_bounds__(512, 1) void pwa_mma_kernel()
{
    extern __shared__ float sm[];
    uint32_t sbase = smem_u32(sm);
    int tid = threadIdx.x, wid = tid >> 5, lane = tid & 31;
    int g = lane >> 2, tg = lane & 3;
    int h = blockIdx.z;
    int i0 = blockIdx.y * 256;
    int nd0 = blockIdx.x * 128;
    const __half* Ah_g = g_whf + (size_t)((i0 >> 4) * 8 + h) * 8192;
    const __half* Bg   = g_vTf + (size_t)(h * 512 + (nd0 >> 3)) * 4096;

    int iw = (wid & 3) * 4;
    int nw = (wid >> 2) * 4;
    int wi = (wid & 3) * 64, wn = (wid >> 2) * 32;

    float acc[4][4][4];
#pragma unroll
    for (int mt = 0; mt < 4; ++mt)
#pragma unroll
        for (int nt = 0; nt < 4; ++nt)
#pragma unroll
            for (int r = 0; r < 4; ++r) acc[mt][nt][r] = 0.f;

    pw_ldstage(sbase, tid, Ah_g, Bg, 0);
    CP_COMMIT();
    pw_ldstage(sbase + PW_STGB, tid, Ah_g, Bg, 1);
    CP_COMMIT();

    for (int c = 0; c < 16; ++c) {
        int slot = c % 3;
        if (c + 2 < 16) {
            pw_ldstage(sbase + ((c + 2) % 3) * PW_STGB, tid, Ah_g, Bg, c + 2);
            CP_COMMIT();
            CP_WAIT(2);
        } else if (c + 1 < 16) {
            CP_WAIT(1);
        } else {
            CP_WAIT(0);
        }
        __syncthreads();

        const __half* Ah2 = (const __half*)sm + (size_t)slot * PW_STGH;
        const __half* Bh2 = Ah2 + 8192;
#pragma unroll
        for (int kk = 0; kk < 2; ++kk) {
            uint4 av[4];
#pragma unroll
            for (int mt = 0; mt < 4; ++mt) {
                int Igl = iw + mt;
                av[mt] = *(const uint4*)(Ah2 + (size_t)((Igl * 2 + kk) * 32 + lane) * 8);
            }
#pragma unroll
            for (int nt = 0; nt < 4; ++nt) {
                int ndgl = nw + nt;
                uint2 bv = *(const uint2*)(Bh2 + (size_t)((ndgl * 2 + kk) * 32 + lane) * 4);
#pragma unroll
                for (int mt = 0; mt < 4; ++mt)
                    mma_f16(acc[mt][nt], (const uint32_t*)&av[mt], bv.x, bv.y);
            }
        }
        __syncthreads();
    }

    float* Cs = sm;
#pragma unroll
    for (int mt = 0; mt < 4; ++mt) {
        int r = wi + mt * 16 + g;
#pragma unroll
        for (int nt = 0; nt < 4; ++nt) {
            int col = wn + nt * 8 + 2 * tg;
            Cs[col * 260 + r]            = acc[mt][nt][0];
            Cs[(col + 1) * 260 + r]      = acc[mt][nt][1];
            Cs[col * 260 + r + 8]        = acc[mt][nt][2];
            Cs[(col + 1) * 260 + r + 8]  = acc[mt][nt][3];
        }
    }
    __syncthreads();
    size_t obase = ((size_t)h * 4096 + nd0) * 512 + i0;
#pragma unroll
    for (int it = 0; it < 16; ++it) {
        int idx = it * 512 + tid;
        int col = idx >> 6, rq = idx & 63;
        float4 ov = *(const float4*)(Cs + col * 260 + rq * 4);
        const __half2* gp = (const __half2*)(g_gTh + obase + (size_t)col * 512 + rq * 4);
        float2 g0 = __half22float2(gp[0]);
        float2 g1 = __half22float2(gp[1]);
        __half2 r0 = __floats2half2_rn(ov.x * g0.x, ov.y * g0.y);
        __half2 r1 = __floats2half2_rn(ov.z * g1.x, ov.w * g1.y);
        uint2 pk;
        pk.x = *(uint32_t*)&r0;
        pk.y = *(uint32_t*)&r1;
        *(uint2*)(g_o2h + obase + (size_t)col * 512 + rq * 4) = pk;
    }
}

// ---------------------------------------------------------------------------
// Kernel 5: outT[c_out][s] = Wout(fp16) @ G(fp16) via m16n8k16 mma.
// Gt [s 128][72 halves] (c contiguous), Wh [c_out 64][72 halves].
// Ds [s 128][68 fp32] aliases Gt region after mma.  All frag LDS vectorized.
// ---------------------------------------------------------------------------
#define OUT_SMEMB 44032
__global__ __launch_bounds__(256, 2) void out_kernel(
    const float* __restrict__ Wout, float* __restrict__ out)
{
    extern __shared__ char so[];
    __half* Gt = (__half*)so;              // [128][72]
    __half* Wh = (__half*)(so + 34816);    // [64][72]
    float*  Ds = (float*)so;               // [128][68] (after mma)
    int tid = threadIdx.x, wid = tid >> 5, lane = tid & 31;
    int g = lane >> 2, tg = lane & 3;
    int n = blockIdx.x & 511, s0 = (blockIdx.x >> 9) * 128;

    // Wout -> Wh fp16 (1024 float4)
#pragma unroll
    for (int it = 0; it < 4; ++it) {
        int idx = it * 256 + tid;
        int co = idx >> 4, q = idx & 15;
        float4 a = *(const float4*)(Wout + co * 64 + q * 4);
        __half2 h0 = __floats2half2_rn(a.x, a.y);
        __half2 h1 = __floats2half2_rn(a.z, a.w);
        uint2 pk;
        pk.x = *(uint32_t*)&h0;
        pk.y = *(uint32_t*)&h1;
        *(uint2*)(Wh + co * 72 + q * 4) = pk;
    }
    // o2h -> Gt transposed [s][c]
#pragma unroll
    for (int it = 0; it < 8; ++it) {
        int idx = it * 256 + tid;
        int c = idx >> 5, sq = idx & 31;
        uint2 v = *(const uint2*)(g_o2h + ((size_t)c * 512 + n) * 512 + s0 + sq * 4);
        const __half* hv = (const __half*)&v;
        Gt[(sq * 4 + 0) * 72 + c] = hv[0];
        Gt[(sq * 4 + 1) * 72 + c] = hv[1];
        Gt[(sq * 4 + 2) * 72 + c] = hv[2];
        Gt[(sq * 4 + 3) * 72 + c] = hv[3];
    }
    __syncthreads();

    // mma: warp = 2 n-tiles (s), all 4 m-tiles (c_out), K=64 (4 k16 steps)
    float acc[4][2][4];
#pragma unroll
    for (int mt = 0; mt < 4; ++mt)
#pragma unroll
        for (int nt = 0; nt < 2; ++nt)
#pragma unroll
            for (int r = 0; r < 4; ++r) acc[mt][nt][r] = 0.f;

#pragma unroll
    for (int ks = 0; ks < 4; ++ks) {
        uint32_t a[4][4];
#pragma unroll
        for (int mt = 0; mt < 4; ++mt) {
            const uint32_t* w0 = (const uint32_t*)(Wh + (mt * 16 + g) * 72);
            const uint32_t* w1 = (const uint32_t*)(Wh + (mt * 16 + g + 8) * 72);
            a[mt][0] = w0[ks * 8 + tg];
            a[mt][1] = w1[ks * 8 + tg];
            a[mt][2] = w0[ks * 8 + tg + 4];
            a[mt][3] = w1[ks * 8 + tg + 4];
        }
#pragma unroll
        for (int nt = 0; nt < 2; ++nt) {
            int col = (wid * 2 + nt) * 8 + g;
            const uint32_t* gr = (const uint32_t*)(Gt + col * 72);
            uint32_t b0 = gr[ks * 8 + tg];
            uint32_t b1 = gr[ks * 8 + tg + 4];
#pragma unroll
            for (int mt = 0; mt < 4; ++mt)
                mma_f16(acc[mt][nt], a[mt], b0, b1);
        }
    }
    __syncthreads();

    // stage C: Ds[s][c_out]
#pragma unroll
    for (int mt = 0; mt < 4; ++mt) {
        int row = mt * 16 + g;
#pragma unroll
        for (int nt = 0; nt < 2; ++nt) {
            int col = (wid * 2 + nt) * 8 + 2 * tg;
            Ds[col * 68 + row]           = acc[mt][nt][0];
            Ds[(col + 1) * 68 + row]     = acc[mt][nt][1];
            Ds[col * 68 + row + 8]       = acc[mt][nt][2];
            Ds[(col + 1) * 68 + row + 8] = acc[mt][nt][3];
        }
    }
    __syncthreads();
#pragma unroll
    for (int it = 0; it < 8; ++it) {
        int idx = it * 256 + tid;
        int s = idx >> 4, cq = idx & 15;
        *(float4*)(out + ((size_t)(s0 + s) * 512 + n) * CM + cq * 4) =
            *(const float4*)(Ds + s * 68 + cq * 4);
    }
}

// ---------------------------------------------------------------------------
extern "C" void kernel_launch(void* const* d_in, const int* in_sizes, int n_in,
                              void* d_out, int out_size)
{
    const float* m    = (const float*)d_in[0];
    const float* z    = (const float*)d_in[1];
    const float* lnmw = (const float*)d_in[2];
    const float* lnmb = (const float*)d_in[3];
    const float* lnzw = (const float*)d_in[4];
    const float* lnzb = (const float*)d_in[5];
    const float* Wv   = (const float*)d_in[6];
    const float* Wb   = (const float*)d_in[7];
    const float* Wg   = (const float*)d_in[8];
    const float* Wout = (const float*)d_in[9];
    float* out = (float*)d_out;

    cudaFuncSetAttribute(pwa_mma_kernel,
                         cudaFuncAttributeMaxDynamicSharedMemorySize, PW_SMEMB);
    cudaFuncSetAttribute(vg_kernel,
                         cudaFuncAttributeMaxDynamicSharedMemorySize, VG_SMEMB);
    cudaFuncSetAttribute(softmax_kernel,
                         cudaFuncAttributeMaxDynamicSharedMemorySize, SMX_SMEMB);
    cudaFuncSetAttribute(out_kernel,
                         cudaFuncAttributeMaxDynamicSharedMemorySize, OUT_SMEMB);

    bias_ln_kernel<<<SQ * SQ / 64, 256>>>(z, lnzw, lnzb, Wb);
    softmax_kernel<<<(SQ / 16) * NH, 256, SMX_SMEMB>>>();
    vg_kernel<<<dim3(512, 4), 256, VG_SMEMB>>>(m, lnmw, lnmb, Wv, Wg);
    dim3 gD(32, 2, NH);
    pwa_mma_kernel<<<gD, 512, PW_SMEMB>>>();
    out_kernel<<<SQ * NSEQ / 128, 256, OUT_SMEMB>>>(Wout, out);
}

// round 15
// speedup vs baseline: 2.0591x; 1.1002x over previous
#include <cuda_runtime.h>
#include <cuda_fp16.h>
#include <cstdint>

#define SQ 512
#define NSEQ 512
#define CM 64
#define CZ 128
#define NH 8
#define EPS 1e-5f

// Scratch (device globals: allocation-free)
__device__ float  g_w[(size_t)SQ * NH * SQ];       // raw logits [i][h][j]
__device__ __half g_whf[(size_t)SQ * NH * SQ];     // w fp16, m16n8k16 A-frag
__device__ __half g_vTf[(size_t)CM * NSEQ * SQ];   // v fp16, m16n8k16 B-frag
__device__ __half g_gTh[(size_t)CM * NSEQ * SQ];   // gate fp16 [(c*512+n)*512 + s]
__device__ __half g_o2h[(size_t)CM * NSEQ * SQ];   // gated o fp16 [(c*512+n)*512 + i]

__device__ __forceinline__ float warp_sum(float v) {
#pragma unroll
    for (int o = 16; o > 0; o >>= 1) v += __shfl_xor_sync(0xffffffffu, v, o);
    return v;
}
__device__ __forceinline__ uint32_t smem_u32(const void* p) {
    uint32_t a;
    asm("{ .reg .u64 t; cvta.to.shared.u64 t, %1; cvt.u32.u64 %0, t; }" : "=r"(a) : "l"(p));
    return a;
}
__device__ __forceinline__ float tf32rn(float x) {
    uint32_t r;
    asm("cvt.rna.tf32.f32 %0, %1;" : "=r"(r) : "f"(x));
    return __uint_as_float(r);
}
__device__ __forceinline__ void mma_tf32(float* d, const uint32_t* a,
                                         uint32_t b0, uint32_t b1) {
    asm volatile(
        "mma.sync.aligned.m16n8k8.row.col.f32.tf32.tf32.f32 "
        "{%0,%1,%2,%3}, {%4,%5,%6,%7}, {%8,%9}, {%0,%1,%2,%3};"
        : "+f"(d[0]), "+f"(d[1]), "+f"(d[2]), "+f"(d[3])
        : "r"(a[0]), "r"(a[1]), "r"(a[2]), "r"(a[3]), "r"(b0), "r"(b1));
}
__device__ __forceinline__ void mma_f16(float* d, const uint32_t* a,
                                        uint32_t b0, uint32_t b1) {
    asm volatile(
        "mma.sync.aligned.m16n8k16.row.col.f32.f16.f16.f32 "
        "{%0,%1,%2,%3}, {%4,%5,%6,%7}, {%8,%9}, {%0,%1,%2,%3};"
        : "+f"(d[0]), "+f"(d[1]), "+f"(d[2]), "+f"(d[3])
        : "r"(a[0]), "r"(a[1]), "r"(a[2]), "r"(a[3]), "r"(b0), "r"(b1));
}
#define CP_ASYNC16(dst, src) \
    asm volatile("cp.async.cg.shared.global [%0], [%1], 16;" :: "r"(dst), "l"(src))
#define CP_COMMIT() asm volatile("cp.async.commit_group;")
#define CP_WAIT(n)  asm volatile("cp.async.wait_group %0;" :: "n"(n))

// ---------------------------------------------------------------------------
// Kernel 1: b[i,h,j] = LN(z[i,j,:]) . W_b[h,:] -> g_w.  (unchanged)
// ---------------------------------------------------------------------------
__global__ __launch_bounds__(256) void bias_ln_kernel(
    const float* __restrict__ z, const float* __restrict__ lnw,
    const float* __restrict__ lnb, const float* __restrict__ Wb)
{
    __shared__ float zn[64 * 132];
    __shared__ float swb[8 * 132];
    __shared__ float bs[2 * 64 * 8];
    int tid = threadIdx.x, wid = tid >> 5, lane = tid & 31;
    int g = lane >> 2, tg = lane & 3;

    {
        int h = tid >> 5;
        *(float4*)(swb + h * 132 + lane * 4) = *(const float4*)(Wb + h * CZ + lane * 4);
    }
    float4 lw = *(const float4*)(lnw + lane * 4);
    float4 lb = *(const float4*)(lnb + lane * 4);

    size_t R0 = (size_t)blockIdx.x * 64;
#pragma unroll
    for (int rr = 0; rr < 8; ++rr) {
        int row = wid * 8 + rr;
        float4 x = *(const float4*)(z + (R0 + row) * CZ + lane * 4);
        float s = warp_sum(x.x + x.y + x.z + x.w);
        float mu = s * (1.0f / CZ);
        float d0 = x.x - mu, d1 = x.y - mu, d2 = x.z - mu, d3 = x.w - mu;
        float q = warp_sum(d0 * d0 + d1 * d1 + d2 * d2 + d3 * d3);
        float rs = rsqrtf(q * (1.0f / CZ) + EPS);
        float4 nv;
        nv.x = d0 * rs * lw.x + lb.x;
        nv.y = d1 * rs * lw.y + lb.y;
        nv.z = d2 * rs * lw.z + lb.z;
        nv.w = d3 * rs * lw.w + lb.w;
        *(float4*)(zn + row * 132 + lane * 4) = nv;
    }
    __syncthreads();

    {
        int wmt = wid & 3, kh = wid >> 2;
        float acc[4] = {0.f, 0.f, 0.f, 0.f};
#pragma unroll
        for (int ks = 0; ks < 8; ++ks) {
            int k = kh * 64 + ks * 8;
            float a0 = zn[(wmt * 16 + g) * 132 + k + tg];
            float a1 = zn[(wmt * 16 + g + 8) * 132 + k + tg];
            float a2 = zn[(wmt * 16 + g) * 132 + k + tg + 4];
            float a3 = zn[(wmt * 16 + g + 8) * 132 + k + tg + 4];
            uint32_t ah[4], al[4];
            float h0 = tf32rn(a0), h1 = tf32rn(a1), h2 = tf32rn(a2), h3 = tf32rn(a3);
            ah[0] = __float_as_uint(h0); ah[1] = __float_as_uint(h1);
            ah[2] = __float_as_uint(h2); ah[3] = __float_as_uint(h3);
            al[0] = __float_as_uint(tf32rn(a0 - h0));
            al[1] = __float_as_uint(tf32rn(a1 - h1));
            al[2] = __float_as_uint(tf32rn(a2 - h2));
            al[3] = __float_as_uint(tf32rn(a3 - h3));
            float b0 = swb[g * 132 + k + tg];
            float b1 = swb[g * 132 + k + tg + 4];
            float bh0 = tf32rn(b0), bh1 = tf32rn(b1);
            uint32_t ubh0 = __float_as_uint(bh0), ubh1 = __float_as_uint(bh1);
            uint32_t ubl0 = __float_as_uint(tf32rn(b0 - bh0));
            uint32_t ubl1 = __float_as_uint(tf32rn(b1 - bh1));
            mma_tf32(acc, ah, ubh0, ubh1);
            mma_tf32(acc, al, ubh0, ubh1);
            mma_tf32(acc, ah, ubl0, ubl1);
        }
        int base = kh * 512 + (wmt * 16 + g) * 8 + 2 * tg;
        bs[base] = acc[0];
        bs[base + 1] = acc[1];
        bs[base + 64] = acc[2];
        bs[base + 65] = acc[3];
    }
    __syncthreads();
    {
        int h = tid >> 6, row = tid & 63;
        float v = bs[row * 8 + h] + bs[512 + row * 8 + h];
        float v2 = bs[row * 8 + h + 4] + bs[512 + row * 8 + h + 4];
        int i = (int)(R0 >> 9), j0 = (int)(R0 & 511);
        g_w[(size_t)i * 4096 + h * 512 + j0 + row] = v;
        g_w[(size_t)i * 4096 + (h + 4) * 512 + j0 + row] = v2;
    }
}

// ---------------------------------------------------------------------------
// Kernel 2: softmax over j; fp16 A-frag slabs.  (unchanged, occ 2)
// ---------------------------------------------------------------------------
#define SMX_SMEMB (8704 * 4)
__global__ __launch_bounds__(256, 2) void softmax_kernel()
{
    extern __shared__ float sx[];
    float* smh = sx;
    int tid = threadIdx.x;
    int row = tid >> 4, l = tid & 15;
    int I = blockIdx.x >> 3, h = blockIdx.x & 7;
    const float* src = g_w + ((size_t)(I * 16 + row)) * 4096 + h * 512;

    float w[32];
    float mx = -1e30f;
#pragma unroll
    for (int jj = 0; jj < 32; ++jj) {
        w[jj] = src[jj * 16 + l];
        mx = fmaxf(mx, w[jj]);
    }
#pragma unroll
    for (int o = 8; o > 0; o >>= 1) mx = fmaxf(mx, __shfl_xor_sync(0xffffffffu, mx, o));
    float sum = 0.f;
#pragma unroll
    for (int jj = 0; jj < 32; ++jj) {
        w[jj] = __expf(w[jj] - mx);
        sum += w[jj];
    }
#pragma unroll
    for (int o = 8; o > 0; o >>= 1) sum += __shfl_xor_sync(0xffffffffu, sum, o);
    float inv = 1.0f / sum;
#pragma unroll
    for (int jj = 0; jj < 32; ++jj) {
        int j = jj * 16 + l;
        smh[j * 17 + row] = w[jj] * inv;
    }
    __syncthreads();

    __half* dh = g_whf + (size_t)(I * 8 + h) * 8192;
#pragma unroll
    for (int it = 0; it < 4; ++it) {
        int u = it * 256 + tid;
        int jg16 = u >> 5, lane = u & 31;
        int gg = lane >> 2, tt = lane & 3;
        __half2 hs[4];
#pragma unroll
        for (int r = 0; r < 4; ++r) {
            int il = gg + (r & 1) * 8;
            int j0 = jg16 * 16 + ((r >> 1) * 8) + 2 * tt;
            hs[r] = __floats2half2_rn(smh[j0 * 17 + il], smh[(j0 + 1) * 17 + il]);
        }
        *(uint4*)(dh + (size_t)u * 8) = *(uint4*)hs;
    }
}

// ---------------------------------------------------------------------------
// Kernel 3: fused LN(m) -> fp16 m16n8k16 mma -> vT (B-frag) + gate.  occ 2.
// Phase 1/2 smem: Ash [128][72] fp16, Bsh [128][72] fp16 (36.9KB).
// Phase 3 smem: Cs/Cg2 fp32 [64][132] each (67.6KB) — peak unchanged.
// ---------------------------------------------------------------------------
#define VG_SMEMB (16896 * 4)

__global__ __launch_bounds__(256, 2) void vg_kernel(
    const float* __restrict__ m, const float* __restrict__ lnw,
    const float* __restrict__ lnb, const float* __restrict__ Wv,
    const float* __restrict__ Wg)
{
    extern __shared__ float sm[];
    __half* Ash = (__half*)sm;                 // [128][72]
    __half* Bsh = Ash + 128 * 72;              // [128][72]
    int tid = threadIdx.x, wid = tid >> 5, lane = tid & 31;
    int g = lane >> 2, tg = lane & 3;
    int n = blockIdx.x, s0 = blockIdx.y * 128;

    {   // phase 1: LN -> fp16 rows; weights -> fp16 rows
        int row = tid >> 1, half = tid & 1;
        const float* src = m + ((size_t)(s0 + row) * 512 + n) * CM + half * 32;
        float v[32];
        float s = 0.f, q = 0.f;
#pragma unroll
        for (int qd = 0; qd < 8; ++qd) {
            float4 a = *(const float4*)(src + qd * 4);
            v[qd * 4 + 0] = a.x; v[qd * 4 + 1] = a.y;
            v[qd * 4 + 2] = a.z; v[qd * 4 + 3] = a.w;
            s += a.x + a.y + a.z + a.w;
            q += a.x * a.x + a.y * a.y + a.z * a.z + a.w * a.w;
        }
        s += __shfl_xor_sync(0xffffffffu, s, 1);
        q += __shfl_xor_sync(0xffffffffu, q, 1);
        float mu = s * (1.0f / CM);
        float var = q * (1.0f / CM) - mu * mu;
        float rs = rsqrtf(var + EPS);
#pragma unroll
        for (int qd = 0; qd < 8; ++qd) {
            int kq = half * 8 + qd;
            float xs[4];
#pragma unroll
            for (int t = 0; t < 4; ++t) {
                int k = kq * 4 + t;
                xs[t] = (v[qd * 4 + t] - mu) * rs * __ldg(lnw + k) + __ldg(lnb + k);
            }
            __half2 h0 = __floats2half2_rn(xs[0], xs[1]);
            __half2 h1 = __floats2half2_rn(xs[2], xs[3]);
            uint2 pk;
            pk.x = *(uint32_t*)&h0;
            pk.y = *(uint32_t*)&h1;
            *(uint2*)(Ash + row * 72 + kq * 4) = pk;
        }
        const float* wsrc = (row < 64) ? (Wv + row * 64) : (Wg + (row - 64) * 64);
#pragma unroll
        for (int qd = 0; qd < 8; ++qd) {
            int kq = half * 8 + qd;
            float4 a = *(const float4*)(wsrc + kq * 4);
            __half2 h0 = __floats2half2_rn(a.x, a.y);
            __half2 h1 = __floats2half2_rn(a.z, a.w);
            uint2 pk;
            pk.x = *(uint32_t*)&h0;
            pk.y = *(uint32_t*)&h1;
            *(uint2*)(Bsh + row * 72 + kq * 4) = pk;
        }
    }
    __syncthreads();

    // phase 2: fp16 mma, 2 m-tiles x 8 n-tiles x 4 k16-steps = 64 mma/warp
    int wi = (wid & 3) * 32, wn = (wid >> 2) * 64;
    float acc[2][8][4];
#pragma unroll
    for (int mt = 0; mt < 2; ++mt)
#pragma unroll
        for (int nt = 0; nt < 8; ++nt)
#pragma unroll
            for (int r = 0; r < 4; ++r) acc[mt][nt][r] = 0.f;

#pragma unroll
    for (int ks = 0; ks < 4; ++ks) {
        int kb = ks * 16 + 2 * tg;
        uint32_t a[2][4];
#pragma unroll
        for (int mt = 0; mt < 2; ++mt) {
            int r0 = wi + mt * 16 + g;
            a[mt][0] = *(const uint32_t*)(Ash + r0 * 72 + kb);
            a[mt][1] = *(const uint32_t*)(Ash + (r0 + 8) * 72 + kb);
            a[mt][2] = *(const uint32_t*)(Ash + r0 * 72 + kb + 8);
            a[mt][3] = *(const uint32_t*)(Ash + (r0 + 8) * 72 + kb + 8);
        }
#pragma unroll
        for (int nt = 0; nt < 8; ++nt) {
            int n0 = wn + nt * 8 + g;
            uint32_t b0 = *(const uint32_t*)(Bsh + n0 * 72 + kb);
            uint32_t b1 = *(const uint32_t*)(Bsh + n0 * 72 + kb + 8);
#pragma unroll
            for (int mt = 0; mt < 2; ++mt)
                mma_f16(acc[mt][nt], a[mt], b0, b1);
        }
    }
    __syncthreads();

    // phase 3: epilogue (unchanged)
    float* Cs = sm;
    float* Cg2 = sm + 8448;
#pragma unroll
    for (int mt = 0; mt < 2; ++mt) {
        int r = wi + mt * 16 + g;
#pragma unroll
        for (int nt = 0; nt < 8; ++nt) {
            int col = wn + nt * 8 + 2 * tg;
            if (wid < 4) {
                Cs[col * 132 + r]            = acc[mt][nt][0];
                Cs[(col + 1) * 132 + r]      = acc[mt][nt][1];
                Cs[col * 132 + r + 8]        = acc[mt][nt][2];
                Cs[(col + 1) * 132 + r + 8]  = acc[mt][nt][3];
            } else {
                int cl = col - 64;
                Cg2[cl * 132 + r]            = 1.0f / (1.0f + __expf(-acc[mt][nt][0]));
                Cg2[(cl + 1) * 132 + r]      = 1.0f / (1.0f + __expf(-acc[mt][nt][1]));
                Cg2[cl * 132 + r + 8]        = 1.0f / (1.0f + __expf(-acc[mt][nt][2]));
                Cg2[(cl + 1) * 132 + r + 8]  = 1.0f / (1.0f + __expf(-acc[mt][nt][3]));
            }
        }
    }
    __syncthreads();
#pragma unroll
    for (int it = 0; it < 8; ++it) {
        int u = it * 256 + tid;
        int c = u >> 5, rem = u & 31;
        int jgl16 = rem >> 2, tt = rem & 3;
        int sl0 = jgl16 * 16 + 2 * tt;
        __half2 p0 = __floats2half2_rn(Cs[c * 132 + sl0], Cs[c * 132 + sl0 + 1]);
        __half2 p1 = __floats2half2_rn(Cs[c * 132 + sl0 + 8], Cs[c * 132 + sl0 + 9]);
        int d = c & 7, hh = c >> 3;
        int ndg = d * 64 + (n >> 3);
        int gpos = n & 7;
        size_t off = ((size_t)hh * 512 + ndg) * 4096
                   + (size_t)((s0 >> 4) + jgl16) * 128 + (gpos * 4 + tt) * 4;
        uint2 pk;
        pk.x = *(uint32_t*)&p0;
        pk.y = *(uint32_t*)&p1;
        *(uint2*)(g_vTf + off) = pk;
    }
#pragma unroll
    for (int it = 0; it < 4; ++it) {
        int idx = it * 256 + tid;
        int c = idx >> 4, s8 = (idx & 15) * 8;
        float4 a = *(const float4*)(Cg2 + c * 132 + s8);
        float4 b = *(const float4*)(Cg2 + c * 132 + s8 + 4);
        __half2 hs[4];
        hs[0] = __floats2half2_rn(a.x, a.y);
        hs[1] = __floats2half2_rn(a.z, a.w);
        hs[2] = __floats2half2_rn(b.x, b.y);
        hs[3] = __floats2half2_rn(b.z, b.w);
        *(uint4*)(g_gTh + ((size_t)c * 512 + n) * 512 + s0 + s8) = *(uint4*)hs;
    }
}

// ---------------------------------------------------------------------------
// Kernel 4: pwa fp16 m16n8k16 mma GEMM.  (exact R13/R14 version — 78us)
// ---------------------------------------------------------------------------
#define PW_STGH 12288
#define PW_STGB 24576
#define PW_SMEMB 133120

__device__ __forceinline__ void pw_ldstage(uint32_t sb, int tid,
                                           const __half* Ah_g, const __half* Bg,
                                           int chunk)
{
    int jg0 = chunk * 2;
#pragma unroll
    for (int it = 0; it < 2; ++it) {
        int t = it * 512 + tid;
        int Igl = t >> 6, rem = t & 63;
        int jgl = rem >> 5, lane = rem & 31;
        size_t src = (size_t)Igl * 65536 + (size_t)(jg0 + jgl) * 256 + lane * 8;
        CP_ASYNC16(sb + (uint32_t)t * 16, Ah_g + src);
    }
    {
        int t = tid;
        int ndgl = t >> 5, rem = t & 31;
        int jgl = rem >> 4, lp = rem & 15;
        size_t src = (size_t)ndgl * 4096 + (size_t)(jg0 + jgl) * 128 + lp * 8;
        CP_ASYNC16(sb + 16384 + (uint32_t)t * 16, Bg + src);
    }
}

__global__ __launch_bounds__(512, 1) void pwa_mma_kernel()
{
    extern __shared__ float sm[];
    uint32_t sbase = smem_u32(sm);
    int tid = threadIdx.x, wid = tid >> 5, lane = tid & 31;
    int g = lane >> 2, tg = lane & 3;
    int h = blockIdx.z;
    int i0 = blockIdx.y * 256;
    int nd0 = blockIdx.x * 128;
    const __half* Ah_g = g_whf + (size_t)((i0 >> 4) * 8 + h) * 8192;
    const __half* Bg   = g_vTf + (size_t)(h * 512 + (nd0 >> 3)) * 4096;

    int iw = (wid & 3) * 4;
    int nw = (wid >> 2) * 4;
    int wi = (wid & 3) * 64, wn = (wid >> 2) * 32;

    float acc[4][4][4];
#pragma unroll
    for (int mt = 0; mt < 4; ++mt)
#pragma unroll
        for (int nt = 0; nt < 4; ++nt)
#pragma unroll
            for (int r = 0; r < 4; ++r) acc[mt][nt][r] = 0.f;

    pw_ldstage(sbase, tid, Ah_g, Bg, 0);
    CP_COMMIT();
    pw_ldstage(sbase + PW_STGB, tid, Ah_g, Bg, 1);
    CP_COMMIT();

    for (int c = 0; c < 16; ++c) {
        int slot = c % 3;
        if (c + 2 < 16) {
            pw_ldstage(sbase + ((c + 2) % 3) * PW_STGB, tid, Ah_g, Bg, c + 2);
            CP_COMMIT();
            CP_WAIT(2);
        } else if (c + 1 < 16) {
            CP_WAIT(1);
        } else {
            CP_WAIT(0);
        }
        __syncthreads();

        const __half* Ah2 = (const __half*)sm + (size_t)slot * PW_STGH;
        const __half* Bh2 = Ah2 + 8192;
#pragma unroll
        for (int kk = 0; kk < 2; ++kk) {
            uint4 av[4];
#pragma unroll
            for (int mt = 0; mt < 4; ++mt) {
                int Igl = iw + mt;
                av[mt] = *(const uint4*)(Ah2 + (size_t)((Igl * 2 + kk) * 32 + lane) * 8);
            }
#pragma unroll
            for (int nt = 0; nt < 4; ++nt) {
                int ndgl = nw + nt;
                uint2 bv = *(const uint2*)(Bh2 + (size_t)((ndgl * 2 + kk) * 32 + lane) * 4);
#pragma unroll
                for (int mt = 0; mt < 4; ++mt)
                    mma_f16(acc[mt][nt], (const uint32_t*)&av[mt], bv.x, bv.y);
            }
        }
        __syncthreads();
    }

    float* Cs = sm;
#pragma unroll
    for (int mt = 0; mt < 4; ++mt) {
        int r = wi + mt * 16 + g;
#pragma unroll
        for (int nt = 0; nt < 4; ++nt) {
            int col = wn + nt * 8 + 2 * tg;
            Cs[col * 260 + r]            = acc[mt][nt][0];
            Cs[(col + 1) * 260 + r]      = acc[mt][nt][1];
            Cs[col * 260 + r + 8]        = acc[mt][nt][2];
            Cs[(col + 1) * 260 + r + 8]  = acc[mt][nt][3];
        }
    }
    __syncthreads();
    size_t obase = ((size_t)h * 4096 + nd0) * 512 + i0;
#pragma unroll
    for (int it = 0; it < 16; ++it) {
        int idx = it * 512 + tid;
        int col = idx >> 6, rq = idx & 63;
        float4 ov = *(const float4*)(Cs + col * 260 + rq * 4);
        const __half2* gp = (const __half2*)(g_gTh + obase + (size_t)col * 512 + rq * 4);
        float2 g0 = __half22float2(gp[0]);
        float2 g1 = __half22float2(gp[1]);
        __half2 r0 = __floats2half2_rn(ov.x * g0.x, ov.y * g0.y);
        __half2 r1 = __floats2half2_rn(ov.z * g1.x, ov.w * g1.y);
        uint2 pk;
        pk.x = *(uint32_t*)&r0;
        pk.y = *(uint32_t*)&r1;
        *(uint2*)(g_o2h + obase + (size_t)col * 512 + rq * 4) = pk;
    }
}

// ---------------------------------------------------------------------------
// Kernel 5: outT = Wout(fp16) @ G(fp16) via m16n8k16 mma.  (unchanged, occ 2)
// ---------------------------------------------------------------------------
#define OUT_SMEMB 44032
__global__ __launch_bounds__(256, 2) void out_kernel(
    const float* __restrict__ Wout, float* __restrict__ out)
{
    extern __shared__ char so[];
    __half* Gt = (__half*)so;
    __half* Wh = (__half*)(so + 34816);
    float*  Ds = (float*)so;
    int tid = threadIdx.x, wid = tid >> 5, lane = tid & 31;
    int g = lane >> 2, tg = lane & 3;
    int n = blockIdx.x & 511, s0 = (blockIdx.x >> 9) * 128;

#pragma unroll
    for (int it = 0; it < 4; ++it) {
        int idx = it * 256 + tid;
        int co = idx >> 4, q = idx & 15;
        float4 a = *(const float4*)(Wout + co * 64 + q * 4);
        __half2 h0 = __floats2half2_rn(a.x, a.y);
        __half2 h1 = __floats2half2_rn(a.z, a.w);
        uint2 pk;
        pk.x = *(uint32_t*)&h0;
        pk.y = *(uint32_t*)&h1;
        *(uint2*)(Wh + co * 72 + q * 4) = pk;
    }
#pragma unroll
    for (int it = 0; it < 8; ++it) {
        int idx = it * 256 + tid;
        int c = idx >> 5, sq = idx & 31;
        uint2 v = *(const uint2*)(g_o2h + ((size_t)c * 512 + n) * 512 + s0 + sq * 4);
        const __half* hv = (const __half*)&v;
        Gt[(sq * 4 + 0) * 72 + c] = hv[0];
        Gt[(sq * 4 + 1) * 72 + c] = hv[1];
        Gt[(sq * 4 + 2) * 72 + c] = hv[2];
        Gt[(sq * 4 + 3) * 72 + c] = hv[3];
    }
    __syncthreads();

    float acc[4][2][4];
#pragma unroll
    for (int mt = 0; mt < 4; ++mt)
#pragma unroll
        for (int nt = 0; nt < 2; ++nt)
#pragma unroll
            for (int r = 0; r < 4; ++r) acc[mt][nt][r] = 0.f;

#pragma unroll
    for (int ks = 0; ks < 4; ++ks) {
        uint32_t a[4][4];
#pragma unroll
        for (int mt = 0; mt < 4; ++mt) {
            const uint32_t* w0 = (const uint32_t*)(Wh + (mt * 16 + g) * 72);
            const uint32_t* w1 = (const uint32_t*)(Wh + (mt * 16 + g + 8) * 72);
            a[mt][0] = w0[ks * 8 + tg];
            a[mt][1] = w1[ks * 8 + tg];
            a[mt][2] = w0[ks * 8 + tg + 4];
            a[mt][3] = w1[ks * 8 + tg + 4];
        }
#pragma unroll
        for (int nt = 0; nt < 2; ++nt) {
            int col = (wid * 2 + nt) * 8 + g;
            const uint32_t* gr = (const uint32_t*)(Gt + col * 72);
            uint32_t b0 = gr[ks * 8 + tg];
            uint32_t b1 = gr[ks * 8 + tg + 4];
#pragma unroll
            for (int mt = 0; mt < 4; ++mt)
                mma_f16(acc[mt][nt], a[mt], b0, b1);
        }
    }
    __syncthreads();

#pragma unroll
    for (int mt = 0; mt < 4; ++mt) {
        int row = mt * 16 + g;
#pragma unroll
        for (int nt = 0; nt < 2; ++nt) {
            int col = (wid * 2 + nt) * 8 + 2 * tg;
            Ds[col * 68 + row]           = acc[mt][nt][0];
            Ds[(col + 1) * 68 + row]     = acc[mt][nt][1];
            Ds[col * 68 + row + 8]       = acc[mt][nt][2];
            Ds[(col + 1) * 68 + row + 8] = acc[mt][nt][3];
        }
    }
    __syncthreads();
#pragma unroll
    for (int it = 0; it < 8; ++it) {
        int idx = it * 256 + tid;
        int s = idx >> 4, cq = idx & 15;
        *(float4*)(out + ((size_t)(s0 + s) * 512 + n) * CM + cq * 4) =
            *(const float4*)(Ds + s * 68 + cq * 4);
    }
}

// ---------------------------------------------------------------------------
extern "C" void kernel_launch(void* const* d_in, const int* in_sizes, int n_in,
                              void* d_out, int out_size)
{
    const float* m    = (const float*)d_in[0];
    const float* z    = (const float*)d_in[1];
    const float* lnmw = (const float*)d_in[2];
    const float* lnmb = (const float*)d_in[3];
    const float* lnzw = (const float*)d_in[4];
    const float* lnzb = (const float*)d_in[5];
    const float* Wv   = (const float*)d_in[6];
    const float* Wb   = (const float*)d_in[7];
    const float* Wg   = (const float*)d_in[8];
    const float* Wout = (const float*)d_in[9];
    float* out = (float*)d_out;

    cudaFuncSetAttribute(pwa_mma_kernel,
                         cudaFuncAttributeMaxDynamicSharedMemorySize, PW_SMEMB);
    cudaFuncSetAttribute(vg_kernel,
                         cudaFuncAttributeMaxDynamicSharedMemorySize, VG_SMEMB);
    cudaFuncSetAttribute(softmax_kernel,
                         cudaFuncAttributeMaxDynamicSharedMemorySize, SMX_SMEMB);
    cudaFuncSetAttribute(out_kernel,
                         cudaFuncAttributeMaxDynamicSharedMemorySize, OUT_SMEMB);

    bias_ln_kernel<<<SQ * SQ / 64, 256>>>(z, lnzw, lnzb, Wb);
    softmax_kernel<<<(SQ / 16) * NH, 256, SMX_SMEMB>>>();
    vg_kernel<<<dim3(512, 4), 256, VG_SMEMB>>>(m, lnmw, lnmb, Wv, Wg);
    dim3 gD(32, 2, NH);
    pwa_mma_kernel<<<gD, 512, PW_SMEMB>>>();
    out_kernel<<<SQ * NSEQ / 128, 256, OUT_SMEMB>>>(Wout, out);
}

// round 16
// speedup vs baseline: 2.1495x; 1.0439x over previous
#include <cuda_runtime.h>
#include <cuda_fp16.h>
#include <cstdint>

#define SQ 512
#define NSEQ 512
#define CM 64
#define CZ 128
#define NH 8
#define EPS 1e-5f

// Scratch (device globals: allocation-free)
__device__ float  g_w[(size_t)SQ * NH * SQ];       // raw logits [i][h][j]
__device__ __half g_whf[(size_t)SQ * NH * SQ];     // w fp16, m16n8k16 A-frag
__device__ __half g_vTf[(size_t)CM * NSEQ * SQ];   // v fp16, m16n8k16 B-frag
__device__ __half g_gTh[(size_t)CM * NSEQ * SQ];   // gate fp16 [(c*512+n)*512 + s]
__device__ __half g_o2h[(size_t)CM * NSEQ * SQ];   // gated o fp16 [(c*512+n)*512 + i]

__device__ __forceinline__ float warp_sum(float v) {
#pragma unroll
    for (int o = 16; o > 0; o >>= 1) v += __shfl_xor_sync(0xffffffffu, v, o);
    return v;
}
__device__ __forceinline__ uint32_t smem_u32(const void* p) {
    uint32_t a;
    asm("{ .reg .u64 t; cvta.to.shared.u64 t, %1; cvt.u32.u64 %0, t; }" : "=r"(a) : "l"(p));
    return a;
}
__device__ __forceinline__ float tf32rn(float x) {
    uint32_t r;
    asm("cvt.rna.tf32.f32 %0, %1;" : "=r"(r) : "f"(x));
    return __uint_as_float(r);
}
__device__ __forceinline__ void mma_tf32(float* d, const uint32_t* a,
                                         uint32_t b0, uint32_t b1) {
    asm volatile(
        "mma.sync.aligned.m16n8k8.row.col.f32.tf32.tf32.f32 "
        "{%0,%1,%2,%3}, {%4,%5,%6,%7}, {%8,%9}, {%0,%1,%2,%3};"
        : "+f"(d[0]), "+f"(d[1]), "+f"(d[2]), "+f"(d[3])
        : "r"(a[0]), "r"(a[1]), "r"(a[2]), "r"(a[3]), "r"(b0), "r"(b1));
}
__device__ __forceinline__ void mma_f16(float* d, const uint32_t* a,
                                        uint32_t b0, uint32_t b1) {
    asm volatile(
        "mma.sync.aligned.m16n8k16.row.col.f32.f16.f16.f32 "
        "{%0,%1,%2,%3}, {%4,%5,%6,%7}, {%8,%9}, {%0,%1,%2,%3};"
        : "+f"(d[0]), "+f"(d[1]), "+f"(d[2]), "+f"(d[3])
        : "r"(a[0]), "r"(a[1]), "r"(a[2]), "r"(a[3]), "r"(b0), "r"(b1));
}
#define CP_ASYNC16(dst, src) \
    asm volatile("cp.async.cg.shared.global [%0], [%1], 16;" :: "r"(dst), "l"(src))
#define CP_COMMIT() asm volatile("cp.async.commit_group;")
#define CP_WAIT(n)  asm volatile("cp.async.wait_group %0;" :: "n"(n))

// ---------------------------------------------------------------------------
// Kernel 1: b[i,h,j] = LN(z[i,j,:]) . W_b[h,:] -> g_w.  (unchanged)
// ---------------------------------------------------------------------------
__global__ __launch_bounds__(256) void bias_ln_kernel(
    const float* __restrict__ z, const float* __restrict__ lnw,
    const float* __restrict__ lnb, const float* __restrict__ Wb)
{
    __shared__ float zn[64 * 132];
    __shared__ float swb[8 * 132];
    __shared__ float bs[2 * 64 * 8];
    int tid = threadIdx.x, wid = tid >> 5, lane = tid & 31;
    int g = lane >> 2, tg = lane & 3;

    {
        int h = tid >> 5;
        *(float4*)(swb + h * 132 + lane * 4) = *(const float4*)(Wb + h * CZ + lane * 4);
    }
    float4 lw = *(const float4*)(lnw + lane * 4);
    float4 lb = *(const float4*)(lnb + lane * 4);

    size_t R0 = (size_t)blockIdx.x * 64;
#pragma unroll
    for (int rr = 0; rr < 8; ++rr) {
        int row = wid * 8 + rr;
        float4 x = *(const float4*)(z + (R0 + row) * CZ + lane * 4);
        float s = warp_sum(x.x + x.y + x.z + x.w);
        float mu = s * (1.0f / CZ);
        float d0 = x.x - mu, d1 = x.y - mu, d2 = x.z - mu, d3 = x.w - mu;
        float q = warp_sum(d0 * d0 + d1 * d1 + d2 * d2 + d3 * d3);
        float rs = rsqrtf(q * (1.0f / CZ) + EPS);
        float4 nv;
        nv.x = d0 * rs * lw.x + lb.x;
        nv.y = d1 * rs * lw.y + lb.y;
        nv.z = d2 * rs * lw.z + lb.z;
        nv.w = d3 * rs * lw.w + lb.w;
        *(float4*)(zn + row * 132 + lane * 4) = nv;
    }
    __syncthreads();

    {
        int wmt = wid & 3, kh = wid >> 2;
        float acc[4] = {0.f, 0.f, 0.f, 0.f};
#pragma unroll
        for (int ks = 0; ks < 8; ++ks) {
            int k = kh * 64 + ks * 8;
            float a0 = zn[(wmt * 16 + g) * 132 + k + tg];
            float a1 = zn[(wmt * 16 + g + 8) * 132 + k + tg];
            float a2 = zn[(wmt * 16 + g) * 132 + k + tg + 4];
            float a3 = zn[(wmt * 16 + g + 8) * 132 + k + tg + 4];
            uint32_t ah[4], al[4];
            float h0 = tf32rn(a0), h1 = tf32rn(a1), h2 = tf32rn(a2), h3 = tf32rn(a3);
            ah[0] = __float_as_uint(h0); ah[1] = __float_as_uint(h1);
            ah[2] = __float_as_uint(h2); ah[3] = __float_as_uint(h3);
            al[0] = __float_as_uint(tf32rn(a0 - h0));
            al[1] = __float_as_uint(tf32rn(a1 - h1));
            al[2] = __float_as_uint(tf32rn(a2 - h2));
            al[3] = __float_as_uint(tf32rn(a3 - h3));
            float b0 = swb[g * 132 + k + tg];
            float b1 = swb[g * 132 + k + tg + 4];
            float bh0 = tf32rn(b0), bh1 = tf32rn(b1);
            uint32_t ubh0 = __float_as_uint(bh0), ubh1 = __float_as_uint(bh1);
            uint32_t ubl0 = __float_as_uint(tf32rn(b0 - bh0));
            uint32_t ubl1 = __float_as_uint(tf32rn(b1 - bh1));
            mma_tf32(acc, ah, ubh0, ubh1);
            mma_tf32(acc, al, ubh0, ubh1);
            mma_tf32(acc, ah, ubl0, ubl1);
        }
        int base = kh * 512 + (wmt * 16 + g) * 8 + 2 * tg;
        bs[base] = acc[0];
        bs[base + 1] = acc[1];
        bs[base + 64] = acc[2];
        bs[base + 65] = acc[3];
    }
    __syncthreads();
    {
        int h = tid >> 6, row = tid & 63;
        float v = bs[row * 8 + h] + bs[512 + row * 8 + h];
        float v2 = bs[row * 8 + h + 4] + bs[512 + row * 8 + h + 4];
        int i = (int)(R0 >> 9), j0 = (int)(R0 & 511);
        g_w[(size_t)i * 4096 + h * 512 + j0 + row] = v;
        g_w[(size_t)i * 4096 + (h + 4) * 512 + j0 + row] = v2;
    }
}

// ---------------------------------------------------------------------------
// Kernel 2: softmax over j; fp16 A-frag slabs.  (unchanged, occ 2)
// ---------------------------------------------------------------------------
#define SMX_SMEMB (8704 * 4)
__global__ __launch_bounds__(256, 2) void softmax_kernel()
{
    extern __shared__ float sx[];
    float* smh = sx;
    int tid = threadIdx.x;
    int row = tid >> 4, l = tid & 15;
    int I = blockIdx.x >> 3, h = blockIdx.x & 7;
    const float* src = g_w + ((size_t)(I * 16 + row)) * 4096 + h * 512;

    float w[32];
    float mx = -1e30f;
#pragma unroll
    for (int jj = 0; jj < 32; ++jj) {
        w[jj] = src[jj * 16 + l];
        mx = fmaxf(mx, w[jj]);
    }
#pragma unroll
    for (int o = 8; o > 0; o >>= 1) mx = fmaxf(mx, __shfl_xor_sync(0xffffffffu, mx, o));
    float sum = 0.f;
#pragma unroll
    for (int jj = 0; jj < 32; ++jj) {
        w[jj] = __expf(w[jj] - mx);
        sum += w[jj];
    }
#pragma unroll
    for (int o = 8; o > 0; o >>= 1) sum += __shfl_xor_sync(0xffffffffu, sum, o);
    float inv = 1.0f / sum;
#pragma unroll
    for (int jj = 0; jj < 32; ++jj) {
        int j = jj * 16 + l;
        smh[j * 17 + row] = w[jj] * inv;
    }
    __syncthreads();

    __half* dh = g_whf + (size_t)(I * 8 + h) * 8192;
#pragma unroll
    for (int it = 0; it < 4; ++it) {
        int u = it * 256 + tid;
        int jg16 = u >> 5, lane = u & 31;
        int gg = lane >> 2, tt = lane & 3;
        __half2 hs[4];
#pragma unroll
        for (int r = 0; r < 4; ++r) {
            int il = gg + (r & 1) * 8;
            int j0 = jg16 * 16 + ((r >> 1) * 8) + 2 * tt;
            hs[r] = __floats2half2_rn(smh[j0 * 17 + il], smh[(j0 + 1) * 17 + il]);
        }
        *(uint4*)(dh + (size_t)u * 8) = *(uint4*)hs;
    }
}

// ---------------------------------------------------------------------------
// Kernel 3: fused LN(m) -> fp16 mma -> vT + gate.  (unchanged, occ 2)
// ---------------------------------------------------------------------------
#define VG_SMEMB (16896 * 4)

__global__ __launch_bounds__(256, 2) void vg_kernel(
    const float* __restrict__ m, const float* __restrict__ lnw,
    const float* __restrict__ lnb, const float* __restrict__ Wv,
    const float* __restrict__ Wg)
{
    extern __shared__ float sm[];
    __half* Ash = (__half*)sm;                 // [128][72]
    __half* Bsh = Ash + 128 * 72;              // [128][72]
    int tid = threadIdx.x, wid = tid >> 5, lane = tid & 31;
    int g = lane >> 2, tg = lane & 3;
    int n = blockIdx.x, s0 = blockIdx.y * 128;

    {
        int row = tid >> 1, half = tid & 1;
        const float* src = m + ((size_t)(s0 + row) * 512 + n) * CM + half * 32;
        float v[32];
        float s = 0.f, q = 0.f;
#pragma unroll
        for (int qd = 0; qd < 8; ++qd) {
            float4 a = *(const float4*)(src + qd * 4);
            v[qd * 4 + 0] = a.x; v[qd * 4 + 1] = a.y;
            v[qd * 4 + 2] = a.z; v[qd * 4 + 3] = a.w;
            s += a.x + a.y + a.z + a.w;
            q += a.x * a.x + a.y * a.y + a.z * a.z + a.w * a.w;
        }
        s += __shfl_xor_sync(0xffffffffu, s, 1);
        q += __shfl_xor_sync(0xffffffffu, q, 1);
        float mu = s * (1.0f / CM);
        float var = q * (1.0f / CM) - mu * mu;
        float rs = rsqrtf(var + EPS);
#pragma unroll
        for (int qd = 0; qd < 8; ++qd) {
            int kq = half * 8 + qd;
            float xs[4];
#pragma unroll
            for (int t = 0; t < 4; ++t) {
                int k = kq * 4 + t;
                xs[t] = (v[qd * 4 + t] - mu) * rs * __ldg(lnw + k) + __ldg(lnb + k);
            }
            __half2 h0 = __floats2half2_rn(xs[0], xs[1]);
            __half2 h1 = __floats2half2_rn(xs[2], xs[3]);
            uint2 pk;
            pk.x = *(uint32_t*)&h0;
            pk.y = *(uint32_t*)&h1;
            *(uint2*)(Ash + row * 72 + kq * 4) = pk;
        }
        const float* wsrc = (row < 64) ? (Wv + row * 64) : (Wg + (row - 64) * 64);
#pragma unroll
        for (int qd = 0; qd < 8; ++qd) {
            int kq = half * 8 + qd;
            float4 a = *(const float4*)(wsrc + kq * 4);
            __half2 h0 = __floats2half2_rn(a.x, a.y);
            __half2 h1 = __floats2half2_rn(a.z, a.w);
            uint2 pk;
            pk.x = *(uint32_t*)&h0;
            pk.y = *(uint32_t*)&h1;
            *(uint2*)(Bsh + row * 72 + kq * 4) = pk;
        }
    }
    __syncthreads();

    int wi = (wid & 3) * 32, wn = (wid >> 2) * 64;
    float acc[2][8][4];
#pragma unroll
    for (int mt = 0; mt < 2; ++mt)
#pragma unroll
        for (int nt = 0; nt < 8; ++nt)
#pragma unroll
            for (int r = 0; r < 4; ++r) acc[mt][nt][r] = 0.f;

#pragma unroll
    for (int ks = 0; ks < 4; ++ks) {
        int kb = ks * 16 + 2 * tg;
        uint32_t a[2][4];
#pragma unroll
        for (int mt = 0; mt < 2; ++mt) {
            int r0 = wi + mt * 16 + g;
            a[mt][0] = *(const uint32_t*)(Ash + r0 * 72 + kb);
            a[mt][1] = *(const uint32_t*)(Ash + (r0 + 8) * 72 + kb);
            a[mt][2] = *(const uint32_t*)(Ash + r0 * 72 + kb + 8);
            a[mt][3] = *(const uint32_t*)(Ash + (r0 + 8) * 72 + kb + 8);
        }
#pragma unroll
        for (int nt = 0; nt < 8; ++nt) {
            int n0 = wn + nt * 8 + g;
            uint32_t b0 = *(const uint32_t*)(Bsh + n0 * 72 + kb);
            uint32_t b1 = *(const uint32_t*)(Bsh + n0 * 72 + kb + 8);
#pragma unroll
            for (int mt = 0; mt < 2; ++mt)
                mma_f16(acc[mt][nt], a[mt], b0, b1);
        }
    }
    __syncthreads();

    float* Cs = sm;
    float* Cg2 = sm + 8448;
#pragma unroll
    for (int mt = 0; mt < 2; ++mt) {
        int r = wi + mt * 16 + g;
#pragma unroll
        for (int nt = 0; nt < 8; ++nt) {
            int col = wn + nt * 8 + 2 * tg;
            if (wid < 4) {
                Cs[col * 132 + r]            = acc[mt][nt][0];
                Cs[(col + 1) * 132 + r]      = acc[mt][nt][1];
                Cs[col * 132 + r + 8]        = acc[mt][nt][2];
                Cs[(col + 1) * 132 + r + 8]  = acc[mt][nt][3];
            } else {
                int cl = col - 64;
                Cg2[cl * 132 + r]            = 1.0f / (1.0f + __expf(-acc[mt][nt][0]));
                Cg2[(cl + 1) * 132 + r]      = 1.0f / (1.0f + __expf(-acc[mt][nt][1]));
                Cg2[cl * 132 + r + 8]        = 1.0f / (1.0f + __expf(-acc[mt][nt][2]));
                Cg2[(cl + 1) * 132 + r + 8]  = 1.0f / (1.0f + __expf(-acc[mt][nt][3]));
            }
        }
    }
    __syncthreads();
#pragma unroll
    for (int it = 0; it < 8; ++it) {
        int u = it * 256 + tid;
        int c = u >> 5, rem = u & 31;
        int jgl16 = rem >> 2, tt = rem & 3;
        int sl0 = jgl16 * 16 + 2 * tt;
        __half2 p0 = __floats2half2_rn(Cs[c * 132 + sl0], Cs[c * 132 + sl0 + 1]);
        __half2 p1 = __floats2half2_rn(Cs[c * 132 + sl0 + 8], Cs[c * 132 + sl0 + 9]);
        int d = c & 7, hh = c >> 3;
        int ndg = d * 64 + (n >> 3);
        int gpos = n & 7;
        size_t off = ((size_t)hh * 512 + ndg) * 4096
                   + (size_t)((s0 >> 4) + jgl16) * 128 + (gpos * 4 + tt) * 4;
        uint2 pk;
        pk.x = *(uint32_t*)&p0;
        pk.y = *(uint32_t*)&p1;
        *(uint2*)(g_vTf + off) = pk;
    }
#pragma unroll
    for (int it = 0; it < 4; ++it) {
        int idx = it * 256 + tid;
        int c = idx >> 4, s8 = (idx & 15) * 8;
        float4 a = *(const float4*)(Cg2 + c * 132 + s8);
        float4 b = *(const float4*)(Cg2 + c * 132 + s8 + 4);
        __half2 hs[4];
        hs[0] = __floats2half2_rn(a.x, a.y);
        hs[1] = __floats2half2_rn(a.z, a.w);
        hs[2] = __floats2half2_rn(b.x, b.y);
        hs[3] = __floats2half2_rn(b.z, b.w);
        *(uint4*)(g_gTh + ((size_t)c * 512 + n) * 512 + s0 + s8) = *(uint4*)hs;
    }
}

// ---------------------------------------------------------------------------
// Kernel 4: pwa fp16 mma, 256 thr, M=128 x N=128, 2 CTAs/SM.
// Stage: A 8KB | B 8KB = 16KB; 3 stages = 48KB.  Epilogue Cs = 67.6KB (peak).
// ---------------------------------------------------------------------------
#define PW_STGH 8192
#define PW_STGB 16384
#define PW_SMEMB 67584

__device__ __forceinline__ void pw_ldstage(uint32_t sb, int tid,
                                           const __half* Ah_g, const __half* Bg,
                                           int chunk)
{
    int jg0 = chunk * 2;
#pragma unroll
    for (int it = 0; it < 2; ++it) {       // A: 512 x 16B (8 Igl)
        int t = it * 256 + tid;
        int Igl = t >> 6, rem = t & 63;
        int jgl = rem >> 5, lane = rem & 31;
        size_t src = (size_t)Igl * 65536 + (size_t)(jg0 + jgl) * 256 + lane * 8;
        CP_ASYNC16(sb + (uint32_t)t * 16, Ah_g + src);
    }
#pragma unroll
    for (int it = 0; it < 2; ++it) {       // B: 512 x 16B (16 ndgl)
        int t = it * 256 + tid;
        int ndgl = t >> 5, rem = t & 31;
        int jgl = rem >> 4, lp = rem & 15;
        size_t src = (size_t)ndgl * 4096 + (size_t)(jg0 + jgl) * 128 + lp * 8;
        CP_ASYNC16(sb + 8192 + (uint32_t)t * 16, Bg + src);
    }
}

__global__ __launch_bounds__(256, 2) void pwa_mma_kernel()
{
    extern __shared__ float sm[];
    uint32_t sbase = smem_u32(sm);
    int tid = threadIdx.x, wid = tid >> 5, lane = tid & 31;
    int g = lane >> 2, tg = lane & 3;
    int h = blockIdx.z;
    int i0 = blockIdx.y * 128;
    int nd0 = blockIdx.x * 128;
    const __half* Ah_g = g_whf + (size_t)((i0 >> 4) * 8 + h) * 8192;
    const __half* Bg   = g_vTf + (size_t)(h * 512 + (nd0 >> 3)) * 4096;

    int iw = (wid & 3) * 2;      // Igl base (2 m-tiles of 16)
    int nw = (wid >> 2) * 8;     // ndgl base (8 n-tiles of 8)
    int wi = (wid & 3) * 32, wn = (wid >> 2) * 64;

    float acc[2][8][4];
#pragma unroll
    for (int mt = 0; mt < 2; ++mt)
#pragma unroll
        for (int nt = 0; nt < 8; ++nt)
#pragma unroll
            for (int r = 0; r < 4; ++r) acc[mt][nt][r] = 0.f;

    pw_ldstage(sbase, tid, Ah_g, Bg, 0);
    CP_COMMIT();
    pw_ldstage(sbase + PW_STGB, tid, Ah_g, Bg, 1);
    CP_COMMIT();

    for (int c = 0; c < 16; ++c) {
        int slot = c % 3;
        if (c + 2 < 16) {
            pw_ldstage(sbase + ((c + 2) % 3) * PW_STGB, tid, Ah_g, Bg, c + 2);
            CP_COMMIT();
            CP_WAIT(2);
        } else if (c + 1 < 16) {
            CP_WAIT(1);
        } else {
            CP_WAIT(0);
        }
        __syncthreads();

        const __half* Ah2 = (const __half*)sm + (size_t)slot * PW_STGH;
        const __half* Bh2 = Ah2 + 4096;
#pragma unroll
        for (int kk = 0; kk < 2; ++kk) {
            uint4 av[2];
#pragma unroll
            for (int mt = 0; mt < 2; ++mt) {
                int Igl = iw + mt;
                av[mt] = *(const uint4*)(Ah2 + (size_t)((Igl * 2 + kk) * 32 + lane) * 8);
            }
#pragma unroll
            for (int nt = 0; nt < 8; ++nt) {
                int ndgl = nw + nt;
                uint2 bv = *(const uint2*)(Bh2 + (size_t)((ndgl * 2 + kk) * 32 + lane) * 4);
#pragma unroll
                for (int mt = 0; mt < 2; ++mt)
                    mma_f16(acc[mt][nt], (const uint32_t*)&av[mt], bv.x, bv.y);
            }
        }
        __syncthreads();
    }

    // epilogue: stage C [col 128][132 rows], fp16 gate-multiply, fp16 store
    float* Cs = sm;
#pragma unroll
    for (int mt = 0; mt < 2; ++mt) {
        int r = wi + mt * 16 + g;
#pragma unroll
        for (int nt = 0; nt < 8; ++nt) {
            int col = wn + nt * 8 + 2 * tg;
            Cs[col * 132 + r]            = acc[mt][nt][0];
            Cs[(col + 1) * 132 + r]      = acc[mt][nt][1];
            Cs[col * 132 + r + 8]        = acc[mt][nt][2];
            Cs[(col + 1) * 132 + r + 8]  = acc[mt][nt][3];
        }
    }
    __syncthreads();
    size_t obase = ((size_t)h * 4096 + nd0) * 512 + i0;
#pragma unroll
    for (int it = 0; it < 16; ++it) {
        int idx = it * 256 + tid;
        int col = idx >> 5, rq = idx & 31;
        float4 ov = *(const float4*)(Cs + col * 132 + rq * 4);
        const __half2* gp = (const __half2*)(g_gTh + obase + (size_t)col * 512 + rq * 4);
        float2 g0 = __half22float2(gp[0]);
        float2 g1 = __half22float2(gp[1]);
        __half2 r0 = __floats2half2_rn(ov.x * g0.x, ov.y * g0.y);
        __half2 r1 = __floats2half2_rn(ov.z * g1.x, ov.w * g1.y);
        uint2 pk;
        pk.x = *(uint32_t*)&r0;
        pk.y = *(uint32_t*)&r1;
        *(uint2*)(g_o2h + obase + (size_t)col * 512 + rq * 4) = pk;
    }
}

// ---------------------------------------------------------------------------
// Kernel 5: outT = Wout(fp16) @ G(fp16) via m16n8k16 mma.  (unchanged, occ 2)
// ---------------------------------------------------------------------------
#define OUT_SMEMB 44032
__global__ __launch_bounds__(256, 2) void out_kernel(
    const float* __restrict__ Wout, float* __restrict__ out)
{
    extern __shared__ char so[];
    __half* Gt = (__half*)so;
    __half* Wh = (__half*)(so + 34816);
    float*  Ds = (float*)so;
    int tid = threadIdx.x, wid = tid >> 5, lane = tid & 31;
    int g = lane >> 2, tg = lane & 3;
    int n = blockIdx.x & 511, s0 = (blockIdx.x >> 9) * 128;

#pragma unroll
    for (int it = 0; it < 4; ++it) {
        int idx = it * 256 + tid;
        int co = idx >> 4, q = idx & 15;
        float4 a = *(const float4*)(Wout + co * 64 + q * 4);
        __half2 h0 = __floats2half2_rn(a.x, a.y);
        __half2 h1 = __floats2half2_rn(a.z, a.w);
        uint2 pk;
        pk.x = *(uint32_t*)&h0;
        pk.y = *(uint32_t*)&h1;
        *(uint2*)(Wh + co * 72 + q * 4) = pk;
    }
#pragma unroll
    for (int it = 0; it < 8; ++it) {
        int idx = it * 256 + tid;
        int c = idx >> 5, sq = idx & 31;
        uint2 v = *(const uint2*)(g_o2h + ((size_t)c * 512 + n) * 512 + s0 + sq * 4);
        const __half* hv = (const __half*)&v;
        Gt[(sq * 4 + 0) * 72 + c] = hv[0];
        Gt[(sq * 4 + 1) * 72 + c] = hv[1];
        Gt[(sq * 4 + 2) * 72 + c] = hv[2];
        Gt[(sq * 4 + 3) * 72 + c] = hv[3];
    }
    __syncthreads();

    float acc[4][2][4];
#pragma unroll
    for (int mt = 0; mt < 4; ++mt)
#pragma unroll
        for (int nt = 0; nt < 2; ++nt)
#pragma unroll
            for (int r = 0; r < 4; ++r) acc[mt][nt][r] = 0.f;

#pragma unroll
    for (int ks = 0; ks < 4; ++ks) {
        uint32_t a[4][4];
#pragma unroll
        for (int mt = 0; mt < 4; ++mt) {
            const uint32_t* w0 = (const uint32_t*)(Wh + (mt * 16 + g) * 72);
            const uint32_t* w1 = (const uint32_t*)(Wh + (mt * 16 + g + 8) * 72);
            a[mt][0] = w0[ks * 8 + tg];
            a[mt][1] = w1[ks * 8 + tg];
            a[mt][2] = w0[ks * 8 + tg + 4];
            a[mt][3] = w1[ks * 8 + tg + 4];
        }
#pragma unroll
        for (int nt = 0; nt < 2; ++nt) {
            int col = (wid * 2 + nt) * 8 + g;
            const uint32_t* gr = (const uint32_t*)(Gt + col * 72);
            uint32_t b0 = gr[ks * 8 + tg];
            uint32_t b1 = gr[ks * 8 + tg + 4];
#pragma unroll
            for (int mt = 0; mt < 4; ++mt)
                mma_f16(acc[mt][nt], a[mt], b0, b1);
        }
    }
    __syncthreads();

#pragma unroll
    for (int mt = 0; mt < 4; ++mt) {
        int row = mt * 16 + g;
#pragma unroll
        for (int nt = 0; nt < 2; ++nt) {
            int col = (wid * 2 + nt) * 8 + 2 * tg;
            Ds[col * 68 + row]           = acc[mt][nt][0];
            Ds[(col + 1) * 68 + row]     = acc[mt][nt][1];
            Ds[col * 68 + row + 8]       = acc[mt][nt][2];
            Ds[(col + 1) * 68 + row + 8] = acc[mt][nt][3];
        }
    }
    __syncthreads();
#pragma unroll
    for (int it = 0; it < 8; ++it) {
        int idx = it * 256 + tid;
        int s = idx >> 4, cq = idx & 15;
        *(float4*)(out + ((size_t)(s0 + s) * 512 + n) * CM + cq * 4) =
            *(const float4*)(Ds + s * 68 + cq * 4);
    }
}

// ---------------------------------------------------------------------------
extern "C" void kernel_launch(void* const* d_in, const int* in_sizes, int n_in,
                              void* d_out, int out_size)
{
    const float* m    = (const float*)d_in[0];
    const float* z    = (const float*)d_in[1];
    const float* lnmw = (const float*)d_in[2];
    const float* lnmb = (const float*)d_in[3];
    const float* lnzw = (const float*)d_in[4];
    const float* lnzb = (const float*)d_in[5];
    const float* Wv   = (const float*)d_in[6];
    const float* Wb   = (const float*)d_in[7];
    const float* Wg   = (const float*)d_in[8];
    const float* Wout = (const float*)d_in[9];
    float* out = (float*)d_out;

    cudaFuncSetAttribute(pwa_mma_kernel,
                         cudaFuncAttributeMaxDynamicSharedMemorySize, PW_SMEMB);
    cudaFuncSetAttribute(vg_kernel,
                         cudaFuncAttributeMaxDynamicSharedMemorySize, VG_SMEMB);
    cudaFuncSetAttribute(softmax_kernel,
                         cudaFuncAttributeMaxDynamicSharedMemorySize, SMX_SMEMB);
    cudaFuncSetAttribute(out_kernel,
                         cudaFuncAttributeMaxDynamicSharedMemorySize, OUT_SMEMB);

    bias_ln_kernel<<<SQ * SQ / 64, 256>>>(z, lnzw, lnzb, Wb);
    softmax_kernel<<<(SQ / 16) * NH, 256, SMX_SMEMB>>>();
    vg_kernel<<<dim3(512, 4), 256, VG_SMEMB>>>(m, lnmw, lnmb, Wv, Wg);
    dim3 gD(32, 4, NH);
    pwa_mma_kernel<<<gD, 256, PW_SMEMB>>>();
    out_kernel<<<SQ * NSEQ / 128, 256, OUT_SMEMB>>>(Wout, out);
}